// round 12
// baseline (speedup 1.0000x reference)
#include <cuda_runtime.h>
#include <cuda_bf16.h>
#include <math.h>
#include <stdint.h>

// ============================================================================
// SimMIM forward, Round 11:
//  - GEMM: CTA 128x256, warp tile 64x64 (8 warps), BK=64, 3-stage cp.async,
//    144KB smem, 1 CTA/SM. Halves SMEM fragment re-read redundancy -> moves
//    the kernel from smem-crossbar-bound (~40% tensor) toward tensor-bound.
//  - Everything else carried from R10 (single-pass LN, smem attention, fused
//    f2b, batched transposes). Embed GEMM at launch index 3 (ncu slot).
// ============================================================================

#define BATCH   64
#define NTOK    196
#define DIM     768
#define QKVDIM  2304
#define MLPDIM  3072
#define HEADS   12
#define DH      64
#define DEPTH   6
#define NMASK   98
#define TOKENS  (BATCH * NTOK)          // 12544 = 98*128
#define TOTELEM ((size_t)TOKENS * DIM)

// ---- fp32 scratch ----
__device__ float  g_patches[TOKENS * DIM];
__device__ float  g_x      [TOKENS * DIM];
__device__ float  g_qkv    [TOKENS * QKVDIM];
__device__ float  g_pred   [TOKENS * DIM];
__device__ int    g_mask   [BATCH * NTOK];
__device__ double g_part   [1024];

// ---- bf16 scratch ----
__device__ __nv_bfloat16 g_pb  [TOKENS * DIM];
__device__ __nv_bfloat16 g_hb  [TOKENS * DIM];
__device__ __nv_bfloat16 g_ab  [TOKENS * DIM];
__device__ __nv_bfloat16 g_xb  [TOKENS * DIM];
__device__ __nv_bfloat16 g_hidb[(size_t)TOKENS * MLPDIM];

// ---- bf16 transposed weights [N,K] ----
__device__ __nv_bfloat16 g_wqkvT[DEPTH * QKVDIM * DIM];
__device__ __nv_bfloat16 g_woT  [DEPTH * DIM * DIM];
__device__ __nv_bfloat16 g_w1T  [DEPTH * MLPDIM * DIM];
__device__ __nv_bfloat16 g_w2T  [(size_t)DEPTH * DIM * MLPDIM];
__device__ __nv_bfloat16 g_pwT  [DIM * DIM];
__device__ __nv_bfloat16 g_pixT [DIM * DIM];

// ============================================================================
// PTX helpers
// ============================================================================
__device__ __forceinline__ uint32_t smem_u32(const void* p) {
    uint32_t a;
    asm("{ .reg .u64 t; cvta.to.shared.u64 t, %1; cvt.u32.u64 %0, t; }"
        : "=r"(a) : "l"(p));
    return a;
}
__device__ __forceinline__ void cp_async16(uint32_t dst, const void* src) {
    asm volatile("cp.async.cg.shared.global [%0], [%1], 16;" :: "r"(dst), "l"(src));
}
__device__ __forceinline__ void cp_commit() {
    asm volatile("cp.async.commit_group;");
}
__device__ __forceinline__ void ldm_x4(uint32_t* r, uint32_t addr) {
    asm volatile("ldmatrix.sync.aligned.m8n8.x4.shared.b16 {%0,%1,%2,%3}, [%4];"
                 : "=r"(r[0]), "=r"(r[1]), "=r"(r[2]), "=r"(r[3]) : "r"(addr));
}
__device__ __forceinline__ void mma16816(float* d, const uint32_t* a, const uint32_t* b) {
    asm volatile(
        "mma.sync.aligned.m16n8k16.row.col.f32.bf16.bf16.f32 "
        "{%0,%1,%2,%3}, {%4,%5,%6,%7}, {%8,%9}, {%0,%1,%2,%3};"
        : "+f"(d[0]), "+f"(d[1]), "+f"(d[2]), "+f"(d[3])
        : "r"(a[0]), "r"(a[1]), "r"(a[2]), "r"(a[3]), "r"(b[0]), "r"(b[1]));
}

// SMEM tile row: 64 bf16 = 128B = 8x16B segs. seg' = seg ^ (row & 7).
// k16-step kk flips the two low seg bits: addr ^ (kk<<5).
__device__ __forceinline__ uint32_t swz64(int row, int seg) {
    return (uint32_t)(row * 128 + ((seg ^ (row & 7)) << 4));
}

// ============================================================================
// small kernels
// ============================================================================
__global__ void patchify_kernel(const float* __restrict__ img) {
    size_t i = (size_t)blockIdx.x * blockDim.x + threadIdx.x;
    if (i >= TOTELEM) return;
    int d  = (int)(i % DIM);
    int n  = (int)((i / DIM) % NTOK);
    int b  = (int)(i / ((size_t)DIM * NTOK));
    int gi = n / 14, gj = n % 14;
    int pi = d / 48; int rem = d % 48; int pj = rem / 3; int c = rem % 3;
    size_t src = (((size_t)b * 224 + gi * 16 + pi) * 224 + (gj * 16 + pj)) * 3 + c;
    float v = img[src];
    g_patches[i] = v;
    g_pb[i] = __float2bfloat16(v);
}

__global__ void topk_kernel(const float* __restrict__ noise) {
    int b = blockIdx.x;
    __shared__ float v[NTOK];
    int t = threadIdx.x;
    if (t < NTOK) v[t] = noise[b * NTOK + t];
    __syncthreads();
    if (t < NTOK) {
        float mv = v[t];
        int rank = 0;
        for (int j = 0; j < NTOK; j++)
            rank += (v[j] > mv) || (v[j] == mv && j < t);
        g_mask[b * NTOK + t] = (rank < NMASK) ? 1 : 0;
    }
}

__global__ void finalize_tokens(const float* __restrict__ pos_emb,
                                const float* __restrict__ mask_token) {
    size_t i = (size_t)blockIdx.x * blockDim.x + threadIdx.x;
    if (i >= TOTELEM) return;
    int d  = (int)(i % DIM);
    int n  = (int)((i / DIM) % NTOK);
    int bn = (int)(i / DIM);
    float pe = pos_emb[(size_t)(n + 1) * DIM + d];
    g_x[i] = g_mask[bn] ? (mask_token[d] + pe) : (g_x[i] + pe);
}

// single-pass LayerNorm -> bf16
__global__ void ln_kernel(const float* __restrict__ x,
                          const float* __restrict__ s,
                          const float* __restrict__ bp,
                          __nv_bfloat16* __restrict__ out) {
    int row = blockIdx.x;
    int t = threadIdx.x;
    int w = t >> 5, lane = t & 31;
    const float* xr = x + (size_t)row * DIM;
    float v0 = xr[t], v1 = xr[t + 256], v2 = xr[t + 512];
    float s1 = v0 + v1 + v2;
    float s2 = v0 * v0 + v1 * v1 + v2 * v2;
    #pragma unroll
    for (int o = 16; o; o >>= 1) {
        s1 += __shfl_xor_sync(0xffffffffu, s1, o);
        s2 += __shfl_xor_sync(0xffffffffu, s2, o);
    }
    __shared__ float r1[8], r2[8];
    if (lane == 0) { r1[w] = s1; r2[w] = s2; }
    __syncthreads();
    float t1 = 0.0f, t2 = 0.0f;
    #pragma unroll
    for (int i = 0; i < 8; i++) { t1 += r1[i]; t2 += r2[i]; }
    float mean = t1 * (1.0f / DIM);
    float var  = t2 * (1.0f / DIM) - mean * mean;
    float rstd = rsqrtf(var + 1e-5f);
    __nv_bfloat16* outr = out + (size_t)row * DIM;
    outr[t]       = __float2bfloat16((v0 - mean) * rstd * s[t]       + bp[t]);
    outr[t + 256] = __float2bfloat16((v1 - mean) * rstd * s[t + 256] + bp[t + 256]);
    outr[t + 512] = __float2bfloat16((v2 - mean) * rstd * s[t + 512] + bp[t + 512]);
}

// W[K,N] fp32 -> Wt[N,K] bf16 (z = layer)
__global__ void transpose_w(const float* __restrict__ W,
                            __nv_bfloat16* __restrict__ Wt, int K, int N) {
    __shared__ float t[32][33];
    W  += (size_t)blockIdx.z * K * N;
    Wt += (size_t)blockIdx.z * N * K;
    int bn = blockIdx.x * 32, bk = blockIdx.y * 32;
    int tx = threadIdx.x, ty = threadIdx.y;
    #pragma unroll
    for (int j = 0; j < 32; j += 8)
        t[ty + j][tx] = W[(size_t)(bk + ty + j) * N + bn + tx];
    __syncthreads();
    #pragma unroll
    for (int j = 0; j < 32; j += 8)
        Wt[(size_t)(bn + ty + j) * K + bk + tx] = __float2bfloat16(t[tx][ty + j]);
}

__device__ __forceinline__ float gelu_f(float x) {
    float x3 = x * x * x;
    return 0.5f * x * (1.0f + tanhf(0.7978845608028654f * (x + 0.044715f * x3)));
}

// ============================================================================
// bf16 tensor-core GEMM: C[M,N] = epi(A[M,K] @ Bt[N,K]^T + bias)
// CTA 128x256, BK=64, 8 warps (2x4), warp tile 64x64.
// 3-stage cp.async (48KB/stage, 144KB smem), one barrier per K-iter.
// EPI: 0=bias, 1=bias+resid, 2=gelu(bias)
// ============================================================================
#define GSTAGE 49152          // A 16KB + B 32KB
#define GSMEM  (3 * GSTAGE)   // 144KB

template<int EPI, bool OF32, bool OB16>
__global__ __launch_bounds__(256) void gemm_mma(
    const __nv_bfloat16* __restrict__ A,
    const __nv_bfloat16* __restrict__ Bt,
    const float* __restrict__ bias,
    const float* __restrict__ resid,
    float* __restrict__ Cf,
    __nv_bfloat16* __restrict__ Cb,
    int N, int K)
{
    extern __shared__ __align__(16) char smem[];  // [3][A 16KB | B 32KB]
    const uint32_t sbase = smem_u32(smem);
    const int tid = threadIdx.x;
    const int wid = tid >> 5, lane = tid & 31;
    const int warpM = wid >> 2;          // 0..1 -> m offset *64
    const int warpN = wid & 3;           // 0..3 -> n offset *64
    const int rowBase = blockIdx.y * 128;
    const int colBase = blockIdx.x * 256;
    const int KCH = K >> 6;

    // cp.async mapping. A: 2 threads/row, 4 segs each. B: 1 thread/row, 8 segs.
    const int arow = tid >> 1;
    const int aseg = (tid & 1) * 4;
    const __nv_bfloat16* aSrc = A  + (size_t)(rowBase + arow) * K + aseg * 8;
    const __nv_bfloat16* bSrc = Bt + (size_t)(colBase + tid) * K;
    uint32_t aOff[4];
    #pragma unroll
    for (int i = 0; i < 4; i++) aOff[i] = swz64(arow, aseg + i);
    const uint32_t bRowOff = (uint32_t)(tid * 128);
    const uint32_t bSw = (uint32_t)(tid & 7);

    // ldmatrix offsets (kk=0; kk flips addr by ^(kk<<5))
    uint32_t offA[4], offB[4];
    #pragma unroll
    for (int mf = 0; mf < 4; mf++)
        offA[mf] = swz64(warpM * 64 + mf * 16 + (lane & 15), (lane >> 4));
    #pragma unroll
    for (int nfp = 0; nfp < 4; nfp++)
        offB[nfp] = 16384u + swz64(warpN * 64 + nfp * 16 + (lane & 7) + ((lane >> 4) << 3),
                                   (lane >> 3) & 1);

    float acc[4][8][4];
    #pragma unroll
    for (int i = 0; i < 4; i++)
        #pragma unroll
        for (int j = 0; j < 8; j++)
            #pragma unroll
            for (int e = 0; e < 4; e++) acc[i][j][e] = 0.0f;

    auto stage_load = [&](int kc, int s) {
        uint32_t st = sbase + (uint32_t)s * GSTAGE;
        const __nv_bfloat16* a = aSrc + kc * 64;
        const __nv_bfloat16* b = bSrc + kc * 64;
        #pragma unroll
        for (int i = 0; i < 4; i++)
            cp_async16(st + aOff[i], a + i * 8);
        #pragma unroll
        for (int i = 0; i < 8; i++)
            cp_async16(st + 16384 + bRowOff + (uint32_t)(((uint32_t)i ^ bSw) << 4),
                       b + i * 8);
        cp_commit();
    };

    stage_load(0, 0);
    if (KCH > 1) stage_load(1, 1);

    int sIdx = 0;
    for (int c = 0; c < KCH; c++) {
        if (c + 1 < KCH) asm volatile("cp.async.wait_group 1;");
        else             asm volatile("cp.async.wait_group 0;");
        __syncthreads();

        if (c + 2 < KCH) {
            int ns = sIdx + 2; if (ns >= 3) ns -= 3;
            stage_load(c + 2, ns);
        }

        uint32_t base = sbase + (uint32_t)sIdx * GSTAGE;
        #pragma unroll
        for (int kk = 0; kk < 4; kk++) {
            uint32_t x = (uint32_t)kk << 5;
            uint32_t afr[4][4];
            #pragma unroll
            for (int mf = 0; mf < 4; mf++) ldm_x4(afr[mf], base + (offA[mf] ^ x));
            uint32_t bfr[8][2];
            #pragma unroll
            for (int nfp = 0; nfp < 4; nfp++) {
                uint32_t r[4];
                ldm_x4(r, base + (offB[nfp] ^ x));
                bfr[nfp * 2][0] = r[0]; bfr[nfp * 2][1] = r[1];
                bfr[nfp * 2 + 1][0] = r[2]; bfr[nfp * 2 + 1][1] = r[3];
            }
            #pragma unroll
            for (int mf = 0; mf < 4; mf++)
                #pragma unroll
                for (int nf = 0; nf < 8; nf++)
                    mma16816(acc[mf][nf], afr[mf], bfr[nf]);
        }
        sIdx++; if (sIdx == 3) sIdx = 0;
    }

    // ---- epilogue straight from registers ----
    const int rq = lane >> 2;
    const int cq = (lane & 3) * 2;
    #pragma unroll
    for (int mf = 0; mf < 4; mf++) {
        #pragma unroll
        for (int nf = 0; nf < 8; nf++) {
            int col = colBase + warpN * 64 + nf * 8 + cq;
            float b0 = bias[col], b1 = bias[col + 1];
            #pragma unroll
            for (int hrow = 0; hrow < 2; hrow++) {
                int row = rowBase + warpM * 64 + mf * 16 + rq + hrow * 8;
                size_t off = (size_t)row * N + col;
                float v0 = acc[mf][nf][hrow * 2 + 0] + b0;
                float v1 = acc[mf][nf][hrow * 2 + 1] + b1;
                if (EPI == 1) {
                    float2 rv = *(const float2*)(resid + off);
                    v0 += rv.x; v1 += rv.y;
                }
                if (EPI == 2) { v0 = gelu_f(v0); v1 = gelu_f(v1); }
                if (OF32) *(float2*)(Cf + off) = make_float2(v0, v1);
                if (OB16) {
                    __nv_bfloat162 h;
                    h.x = __float2bfloat16(v0); h.y = __float2bfloat16(v1);
                    *(__nv_bfloat162*)(Cb + off) = h;
                }
            }
        }
    }
}

// ============================================================================
// Attention: K/V staged fp32 in SMEM once per (b,h) block.
// ============================================================================
#define ASMEM ((2 * NTOK * DH + 8 * DH + 8 * 200) * 4)

__global__ __launch_bounds__(256) void attn_kernel(const float* __restrict__ qkv,
                                                   __nv_bfloat16* __restrict__ out) {
    extern __shared__ float asm_f[];
    float* Ks = asm_f;
    float* Vs = asm_f + NTOK * DH;
    float* qs = Vs + NTOK * DH;
    float* ps = qs + 8 * DH;

    int bh = blockIdx.x;
    int b = bh / HEADS, h = bh % HEADS;
    const float* Qb = qkv + (size_t)b * NTOK * QKVDIM + h * DH;
    const float* Kb = Qb + DIM;
    const float* Vb = Qb + 2 * DIM;
    int tid = threadIdx.x;
    int w = tid >> 5, lane = tid & 31;

    for (int idx = tid; idx < NTOK * DH; idx += 256) {
        int k = idx >> 6, d = idx & 63;
        Ks[k * 64 + (d ^ (k & 31))] = Kb[(size_t)k * QKVDIM + d];
        Vs[idx] = Vb[(size_t)k * QKVDIM + d];
    }
    __syncthreads();

    for (int q = w; q < NTOK; q += 8) {
        for (int d = lane; d < DH; d += 32)
            qs[w * DH + d] = Qb[(size_t)q * QKVDIM + d];
        __syncwarp();

        float sc[7];
        float mx = -1e30f;
        #pragma unroll
        for (int i = 0; i < 7; i++) {
            int k = lane + i * 32;
            float s = -1e30f;
            if (k < NTOK) {
                const float* kr = Ks + k * 64;
                int cx = k & 31;
                float acc = 0.0f;
                #pragma unroll
                for (int d = 0; d < DH; d++) acc += qs[w * DH + d] * kr[d ^ cx];
                s = acc * 0.125f;
            }
            sc[i] = s;
            mx = fmaxf(mx, s);
        }
        #pragma unroll
        for (int o = 16; o; o >>= 1) mx = fmaxf(mx, __shfl_xor_sync(0xffffffffu, mx, o));

        float sum = 0.0f;
        #pragma unroll
        for (int i = 0; i < 7; i++) {
            int k = lane + i * 32;
            float e = (k < NTOK) ? __expf(sc[i] - mx) : 0.0f;
            sc[i] = e;
            sum += e;
        }
        #pragma unroll
        for (int o = 16; o; o >>= 1) sum += __shfl_xor_sync(0xffffffffu, sum, o);
        float inv = 1.0f / sum;

        #pragma unroll
        for (int i = 0; i < 7; i++) {
            int k = lane + i * 32;
            if (k < NTOK) ps[w * 200 + k] = sc[i] * inv;
        }
        __syncwarp();

        float a0 = 0.0f, a1 = 0.0f;
        int d0 = lane, d1 = lane + 32;
        for (int k = 0; k < NTOK; k++) {
            float p = ps[w * 200 + k];
            a0 += p * Vs[k * 64 + d0];
            a1 += p * Vs[k * 64 + d1];
        }
        size_t o = ((size_t)b * NTOK + q) * DIM + h * DH;
        out[o + d0] = __float2bfloat16(a0);
        out[o + d1] = __float2bfloat16(a1);
        __syncwarp();
    }
}

// ============================================================================
// Loss
// ============================================================================
__global__ void loss_partial_kernel() {
    double acc = 0.0;
    for (size_t i = (size_t)blockIdx.x * blockDim.x + threadIdx.x;
         i < TOTELEM; i += (size_t)gridDim.x * blockDim.x) {
        int bn = (int)(i / DIM);
        if (g_mask[bn]) acc += fabs((double)g_pred[i] - (double)g_patches[i]);
    }
    __shared__ double red[256];
    red[threadIdx.x] = acc;
    __syncthreads();
    for (int o = 128; o; o >>= 1) {
        if (threadIdx.x < o) red[threadIdx.x] += red[threadIdx.x + o];
        __syncthreads();
    }
    if (threadIdx.x == 0) g_part[blockIdx.x] = red[0];
}

__global__ void loss_final_kernel(float* out) {
    __shared__ double red[256];
    int t = threadIdx.x;
    double a = 0.0;
    for (int i = t; i < 1024; i += 256) a += g_part[i];
    red[t] = a;
    __syncthreads();
    for (int o = 128; o; o >>= 1) { if (t < o) red[t] += red[t + o]; __syncthreads(); }
    if (t == 0) out[0] = (float)(red[0] / (4816896.0 * 98.0));
}

// ============================================================================
// Launch (embed GEMM at launch index 3 = the ncu-captured slot)
// ============================================================================
extern "C" void kernel_launch(void* const* d_in, const int* in_sizes, int n_in,
                              void* d_out, int out_size) {
    const float* img        = (const float*)d_in[0];
    const float* mask_noise = (const float*)d_in[1];
    const float* patch_w    = (const float*)d_in[2];
    const float* patch_b    = (const float*)d_in[3];
    const float* pos_emb    = (const float*)d_in[4];
    const float* mask_token = (const float*)d_in[5];
    const float* ln1_s      = (const float*)d_in[6];
    const float* ln1_b      = (const float*)d_in[7];
    const float* wqkv       = (const float*)d_in[8];
    const float* bqkv       = (const float*)d_in[9];
    const float* wo         = (const float*)d_in[10];
    const float* bo         = (const float*)d_in[11];
    const float* ln2_s      = (const float*)d_in[12];
    const float* ln2_b      = (const float*)d_in[13];
    const float* w1         = (const float*)d_in[14];
    const float* b1         = (const float*)d_in[15];
    const float* w2         = (const float*)d_in[16];
    const float* b2         = (const float*)d_in[17];
    const float* pix_w      = (const float*)d_in[18];
    const float* pix_b      = (const float*)d_in[19];
    float* out = (float*)d_out;

    float *x, *qkv, *pred;
    __nv_bfloat16 *pb, *hb, *ab, *xb, *hidb;
    __nv_bfloat16 *wqkvT, *woT, *w1T, *w2T, *pwT, *pixT;
    cudaGetSymbolAddress((void**)&x,     g_x);
    cudaGetSymbolAddress((void**)&qkv,   g_qkv);
    cudaGetSymbolAddress((void**)&pred,  g_pred);
    cudaGetSymbolAddress((void**)&pb,    g_pb);
    cudaGetSymbolAddress((void**)&hb,    g_hb);
    cudaGetSymbolAddress((void**)&ab,    g_ab);
    cudaGetSymbolAddress((void**)&xb,    g_xb);
    cudaGetSymbolAddress((void**)&hidb,  g_hidb);
    cudaGetSymbolAddress((void**)&wqkvT, g_wqkvT);
    cudaGetSymbolAddress((void**)&woT,   g_woT);
    cudaGetSymbolAddress((void**)&w1T,   g_w1T);
    cudaGetSymbolAddress((void**)&w2T,   g_w2T);
    cudaGetSymbolAddress((void**)&pwT,   g_pwT);
    cudaGetSymbolAddress((void**)&pixT,  g_pixT);

    cudaFuncSetAttribute(gemm_mma<0, true,  false>, cudaFuncAttributeMaxDynamicSharedMemorySize, GSMEM);
    cudaFuncSetAttribute(gemm_mma<1, true,  false>, cudaFuncAttributeMaxDynamicSharedMemorySize, GSMEM);
    cudaFuncSetAttribute(gemm_mma<1, true,  true >, cudaFuncAttributeMaxDynamicSharedMemorySize, GSMEM);
    cudaFuncSetAttribute(gemm_mma<2, false, true >, cudaFuncAttributeMaxDynamicSharedMemorySize, GSMEM);
    cudaFuncSetAttribute(attn_kernel, cudaFuncAttributeMaxDynamicSharedMemorySize, ASMEM);

    int eltBlocks = (int)((TOTELEM + 255) / 256);
    dim3 tb(32, 8);

    // launches 0..2
    patchify_kernel<<<eltBlocks, 256>>>(img);                               // 0
    transpose_w<<<dim3(DIM / 32, DIM / 32), tb>>>(patch_w, pwT, DIM, DIM);  // 1
    topk_kernel<<<BATCH, 256>>>(mask_noise);                                // 2
    // launch 3: profiled embed GEMM
    gemm_mma<0, true, false><<<dim3(DIM / 256, TOKENS / 128), 256, GSMEM>>>(
        pb, pwT, patch_b, nullptr, x, nullptr, DIM, DIM);                   // 3

    finalize_tokens<<<eltBlocks, 256>>>(pos_emb, mask_token);

    // batched weight transposes (z = layer)
    transpose_w<<<dim3(DIM / 32, DIM / 32), tb>>>(pix_w, pixT, DIM, DIM);
    transpose_w<<<dim3(QKVDIM / 32, DIM / 32, DEPTH), tb>>>(wqkv, wqkvT, DIM, QKVDIM);
    transpose_w<<<dim3(DIM / 32, DIM / 32, DEPTH), tb>>>(wo, woT, DIM, DIM);
    transpose_w<<<dim3(MLPDIM / 32, DIM / 32, DEPTH), tb>>>(w1, w1T, DIM, MLPDIM);
    transpose_w<<<dim3(DIM / 32, MLPDIM / 32, DEPTH), tb>>>(w2, w2T, MLPDIM, DIM);

    for (int l = 0; l < DEPTH; l++) {
        ln_kernel<<<TOKENS, 256>>>(x, ln1_s + l * DIM, ln1_b + l * DIM, hb);
        gemm_mma<0, true, false><<<dim3(QKVDIM / 256, TOKENS / 128), 256, GSMEM>>>(
            hb, wqkvT + (size_t)l * QKVDIM * DIM, bqkv + l * QKVDIM, nullptr,
            qkv, nullptr, QKVDIM, DIM);
        attn_kernel<<<BATCH * HEADS, 256, ASMEM>>>(qkv, ab);
        gemm_mma<1, true, false><<<dim3(DIM / 256, TOKENS / 128), 256, GSMEM>>>(
            ab, woT + (size_t)l * DIM * DIM, bo + l * DIM, x,
            x, nullptr, DIM, DIM);
        ln_kernel<<<TOKENS, 256>>>(x, ln2_s + l * DIM, ln2_b + l * DIM, hb);
        gemm_mma<2, false, true><<<dim3(MLPDIM / 256, TOKENS / 128), 256, GSMEM>>>(
            hb, w1T + (size_t)l * MLPDIM * DIM, b1 + l * MLPDIM, nullptr,
            nullptr, hidb, MLPDIM, DIM);
        if (l < DEPTH - 1) {
            gemm_mma<1, true, false><<<dim3(DIM / 256, TOKENS / 128), 256, GSMEM>>>(
                hidb, w2T + (size_t)l * DIM * MLPDIM, b2 + l * DIM, x,
                x, nullptr, DIM, MLPDIM);
        } else {
            gemm_mma<1, true, true><<<dim3(DIM / 256, TOKENS / 128), 256, GSMEM>>>(
                hidb, w2T + (size_t)l * DIM * MLPDIM, b2 + l * DIM, x,
                x, xb, DIM, MLPDIM);
        }
    }

    // pixel head
    gemm_mma<0, true, false><<<dim3(DIM / 256, TOKENS / 128), 256, GSMEM>>>(
        xb, pixT, pix_b, nullptr, pred, nullptr, DIM, DIM);

    loss_partial_kernel<<<1024, 256>>>();
    loss_final_kernel<<<1, 256>>>(out);
}

// round 13
// speedup vs baseline: 1.1450x; 1.1450x over previous
#include <cuda_runtime.h>
#include <cuda_bf16.h>
#include <math.h>
#include <stdint.h>

// ============================================================================
// SimMIM forward, Round 12:
//  - GEMM reverted to R10 shape (CTA 128x128, warp 64x32, BK=64, 3-stage,
//    2 CTAs/SM) + B fragments via 2x ldm_x4 (6 LDSM/kk instead of 8).
//  - Attention: K stored as swizzled float4 units (u ^ (k&7)) -> 4x fewer
//    LDS issues in QK; V read as float2 pairs in AV.
//  - Embed GEMM at launch index 3 (ncu slot).
// ============================================================================

#define BATCH   64
#define NTOK    196
#define DIM     768
#define QKVDIM  2304
#define MLPDIM  3072
#define HEADS   12
#define DH      64
#define DEPTH   6
#define NMASK   98
#define TOKENS  (BATCH * NTOK)          // 12544 = 98*128
#define TOTELEM ((size_t)TOKENS * DIM)

// ---- fp32 scratch ----
__device__ float  g_patches[TOKENS * DIM];
__device__ float  g_x      [TOKENS * DIM];
__device__ float  g_qkv    [TOKENS * QKVDIM];
__device__ float  g_pred   [TOKENS * DIM];
__device__ int    g_mask   [BATCH * NTOK];
__device__ double g_part   [1024];

// ---- bf16 scratch ----
__device__ __nv_bfloat16 g_pb  [TOKENS * DIM];
__device__ __nv_bfloat16 g_hb  [TOKENS * DIM];
__device__ __nv_bfloat16 g_ab  [TOKENS * DIM];
__device__ __nv_bfloat16 g_xb  [TOKENS * DIM];
__device__ __nv_bfloat16 g_hidb[(size_t)TOKENS * MLPDIM];

// ---- bf16 transposed weights [N,K] ----
__device__ __nv_bfloat16 g_wqkvT[DEPTH * QKVDIM * DIM];
__device__ __nv_bfloat16 g_woT  [DEPTH * DIM * DIM];
__device__ __nv_bfloat16 g_w1T  [DEPTH * MLPDIM * DIM];
__device__ __nv_bfloat16 g_w2T  [(size_t)DEPTH * DIM * MLPDIM];
__device__ __nv_bfloat16 g_pwT  [DIM * DIM];
__device__ __nv_bfloat16 g_pixT [DIM * DIM];

// ============================================================================
// PTX helpers
// ============================================================================
__device__ __forceinline__ uint32_t smem_u32(const void* p) {
    uint32_t a;
    asm("{ .reg .u64 t; cvta.to.shared.u64 t, %1; cvt.u32.u64 %0, t; }"
        : "=r"(a) : "l"(p));
    return a;
}
__device__ __forceinline__ void cp_async16(uint32_t dst, const void* src) {
    asm volatile("cp.async.cg.shared.global [%0], [%1], 16;" :: "r"(dst), "l"(src));
}
__device__ __forceinline__ void cp_commit() {
    asm volatile("cp.async.commit_group;");
}
__device__ __forceinline__ void ldm_x4(uint32_t* r, uint32_t addr) {
    asm volatile("ldmatrix.sync.aligned.m8n8.x4.shared.b16 {%0,%1,%2,%3}, [%4];"
                 : "=r"(r[0]), "=r"(r[1]), "=r"(r[2]), "=r"(r[3]) : "r"(addr));
}
__device__ __forceinline__ void mma16816(float* d, const uint32_t* a, const uint32_t* b) {
    asm volatile(
        "mma.sync.aligned.m16n8k16.row.col.f32.bf16.bf16.f32 "
        "{%0,%1,%2,%3}, {%4,%5,%6,%7}, {%8,%9}, {%0,%1,%2,%3};"
        : "+f"(d[0]), "+f"(d[1]), "+f"(d[2]), "+f"(d[3])
        : "r"(a[0]), "r"(a[1]), "r"(a[2]), "r"(a[3]), "r"(b[0]), "r"(b[1]));
}

// SMEM GEMM tile: 128 rows x 64 bf16 (128B/row = 8x16B segs).
// seg' = seg ^ (row & 7). k16-step kk flips addr by ^(kk<<5).
__device__ __forceinline__ uint32_t swz64(int row, int seg) {
    return (uint32_t)(row * 128 + ((seg ^ (row & 7)) << 4));
}

// ============================================================================
// small kernels
// ============================================================================
__global__ void patchify_kernel(const float* __restrict__ img) {
    size_t i = (size_t)blockIdx.x * blockDim.x + threadIdx.x;
    if (i >= TOTELEM) return;
    int d  = (int)(i % DIM);
    int n  = (int)((i / DIM) % NTOK);
    int b  = (int)(i / ((size_t)DIM * NTOK));
    int gi = n / 14, gj = n % 14;
    int pi = d / 48; int rem = d % 48; int pj = rem / 3; int c = rem % 3;
    size_t src = (((size_t)b * 224 + gi * 16 + pi) * 224 + (gj * 16 + pj)) * 3 + c;
    float v = img[src];
    g_patches[i] = v;
    g_pb[i] = __float2bfloat16(v);
}

__global__ void topk_kernel(const float* __restrict__ noise) {
    int b = blockIdx.x;
    __shared__ float v[NTOK];
    int t = threadIdx.x;
    if (t < NTOK) v[t] = noise[b * NTOK + t];
    __syncthreads();
    if (t < NTOK) {
        float mv = v[t];
        int rank = 0;
        for (int j = 0; j < NTOK; j++)
            rank += (v[j] > mv) || (v[j] == mv && j < t);
        g_mask[b * NTOK + t] = (rank < NMASK) ? 1 : 0;
    }
}

__global__ void finalize_tokens(const float* __restrict__ pos_emb,
                                const float* __restrict__ mask_token) {
    size_t i = (size_t)blockIdx.x * blockDim.x + threadIdx.x;
    if (i >= TOTELEM) return;
    int d  = (int)(i % DIM);
    int n  = (int)((i / DIM) % NTOK);
    int bn = (int)(i / DIM);
    float pe = pos_emb[(size_t)(n + 1) * DIM + d];
    g_x[i] = g_mask[bn] ? (mask_token[d] + pe) : (g_x[i] + pe);
}

// single-pass LayerNorm -> bf16
__global__ void ln_kernel(const float* __restrict__ x,
                          const float* __restrict__ s,
                          const float* __restrict__ bp,
                          __nv_bfloat16* __restrict__ out) {
    int row = blockIdx.x;
    int t = threadIdx.x;
    int w = t >> 5, lane = t & 31;
    const float* xr = x + (size_t)row * DIM;
    float v0 = xr[t], v1 = xr[t + 256], v2 = xr[t + 512];
    float s1 = v0 + v1 + v2;
    float s2 = v0 * v0 + v1 * v1 + v2 * v2;
    #pragma unroll
    for (int o = 16; o; o >>= 1) {
        s1 += __shfl_xor_sync(0xffffffffu, s1, o);
        s2 += __shfl_xor_sync(0xffffffffu, s2, o);
    }
    __shared__ float r1[8], r2[8];
    if (lane == 0) { r1[w] = s1; r2[w] = s2; }
    __syncthreads();
    float t1 = 0.0f, t2 = 0.0f;
    #pragma unroll
    for (int i = 0; i < 8; i++) { t1 += r1[i]; t2 += r2[i]; }
    float mean = t1 * (1.0f / DIM);
    float var  = t2 * (1.0f / DIM) - mean * mean;
    float rstd = rsqrtf(var + 1e-5f);
    __nv_bfloat16* outr = out + (size_t)row * DIM;
    outr[t]       = __float2bfloat16((v0 - mean) * rstd * s[t]       + bp[t]);
    outr[t + 256] = __float2bfloat16((v1 - mean) * rstd * s[t + 256] + bp[t + 256]);
    outr[t + 512] = __float2bfloat16((v2 - mean) * rstd * s[t + 512] + bp[t + 512]);
}

// W[K,N] fp32 -> Wt[N,K] bf16 (z = layer)
__global__ void transpose_w(const float* __restrict__ W,
                            __nv_bfloat16* __restrict__ Wt, int K, int N) {
    __shared__ float t[32][33];
    W  += (size_t)blockIdx.z * K * N;
    Wt += (size_t)blockIdx.z * N * K;
    int bn = blockIdx.x * 32, bk = blockIdx.y * 32;
    int tx = threadIdx.x, ty = threadIdx.y;
    #pragma unroll
    for (int j = 0; j < 32; j += 8)
        t[ty + j][tx] = W[(size_t)(bk + ty + j) * N + bn + tx];
    __syncthreads();
    #pragma unroll
    for (int j = 0; j < 32; j += 8)
        Wt[(size_t)(bn + ty + j) * K + bk + tx] = __float2bfloat16(t[tx][ty + j]);
}

__device__ __forceinline__ float gelu_f(float x) {
    float x3 = x * x * x;
    return 0.5f * x * (1.0f + tanhf(0.7978845608028654f * (x + 0.044715f * x3)));
}

// ============================================================================
// bf16 tensor-core GEMM: C[M,N] = epi(A[M,K] @ Bt[N,K]^T + bias)
// CTA 128x128, BK=64, 8 warps (2x4), warp tile 64x32.
// 3-stage cp.async (96KB smem, 2 CTAs/SM), one barrier per K-iter.
// B fragments loaded with 2x ldm_x4 per kk (6 LDSM total per kk).
// EPI: 0=bias, 1=bias+resid, 2=gelu(bias)
// ============================================================================
#define GSTAGE 32768
#define GSMEM  (3 * GSTAGE)

template<int EPI, bool OF32, bool OB16>
__global__ __launch_bounds__(256) void gemm_mma(
    const __nv_bfloat16* __restrict__ A,
    const __nv_bfloat16* __restrict__ Bt,
    const float* __restrict__ bias,
    const float* __restrict__ resid,
    float* __restrict__ Cf,
    __nv_bfloat16* __restrict__ Cb,
    int N, int K)
{
    extern __shared__ __align__(16) char smem[];  // [3][A 16KB | B 16KB]
    const uint32_t sbase = smem_u32(smem);
    const int tid = threadIdx.x;
    const int wid = tid >> 5, lane = tid & 31;
    const int warpM = wid >> 2;
    const int warpN = wid & 3;
    const int rowBase = blockIdx.y * 128;
    const int colBase = blockIdx.x * 128;
    const int KCH = K >> 6;

    const int lrow = tid >> 1;
    const int lseg = (tid & 1) * 4;
    const __nv_bfloat16* aSrc = A  + (size_t)(rowBase + lrow) * K + lseg * 8;
    const __nv_bfloat16* bSrc = Bt + (size_t)(colBase + lrow) * K + lseg * 8;
    uint32_t dOff[4];
    #pragma unroll
    for (int i = 0; i < 4; i++) dOff[i] = swz64(lrow, lseg + i);

    // ldmatrix offsets (kk=0; kk flips addr by ^(kk<<5))
    uint32_t offA[4], offB[2];
    #pragma unroll
    for (int mf = 0; mf < 4; mf++)
        offA[mf] = swz64(warpM * 64 + mf * 16 + (lane & 15), (lane >> 4));
    #pragma unroll
    for (int p = 0; p < 2; p++)
        offB[p] = 16384u + swz64(warpN * 32 + p * 16 + (lane & 7) + ((lane >> 4) << 3),
                                 (lane >> 3) & 1);

    float acc[4][4][4];
    #pragma unroll
    for (int i = 0; i < 4; i++)
        #pragma unroll
        for (int j = 0; j < 4; j++)
            #pragma unroll
            for (int e = 0; e < 4; e++) acc[i][j][e] = 0.0f;

    auto stage_load = [&](int kc, int s) {
        uint32_t st = sbase + (uint32_t)s * GSTAGE;
        const __nv_bfloat16* a = aSrc + kc * 64;
        const __nv_bfloat16* b = bSrc + kc * 64;
        #pragma unroll
        for (int i = 0; i < 4; i++) {
            cp_async16(st + dOff[i], a + i * 8);
            cp_async16(st + 16384 + dOff[i], b + i * 8);
        }
        cp_commit();
    };

    stage_load(0, 0);
    if (KCH > 1) stage_load(1, 1);

    int sIdx = 0;
    for (int c = 0; c < KCH; c++) {
        if (c + 1 < KCH) asm volatile("cp.async.wait_group 1;");
        else             asm volatile("cp.async.wait_group 0;");
        __syncthreads();

        if (c + 2 < KCH) {
            int ns = sIdx + 2; if (ns >= 3) ns -= 3;
            stage_load(c + 2, ns);
        }

        uint32_t base = sbase + (uint32_t)sIdx * GSTAGE;
        #pragma unroll
        for (int kk = 0; kk < 4; kk++) {
            uint32_t x = (uint32_t)kk << 5;
            uint32_t afr[4][4];
            #pragma unroll
            for (int mf = 0; mf < 4; mf++) ldm_x4(afr[mf], base + (offA[mf] ^ x));
            uint32_t bfr[4][2];
            #pragma unroll
            for (int p = 0; p < 2; p++) {
                uint32_t r[4];
                ldm_x4(r, base + (offB[p] ^ x));
                bfr[p * 2][0] = r[0]; bfr[p * 2][1] = r[1];
                bfr[p * 2 + 1][0] = r[2]; bfr[p * 2 + 1][1] = r[3];
            }
            #pragma unroll
            for (int mf = 0; mf < 4; mf++)
                #pragma unroll
                for (int nf = 0; nf < 4; nf++)
                    mma16816(acc[mf][nf], afr[mf], bfr[nf]);
        }
        sIdx++; if (sIdx == 3) sIdx = 0;
    }

    // ---- epilogue straight from registers ----
    const int rq = lane >> 2;
    const int cq = (lane & 3) * 2;
    #pragma unroll
    for (int mf = 0; mf < 4; mf++) {
        #pragma unroll
        for (int nf = 0; nf < 4; nf++) {
            int col = colBase + warpN * 32 + nf * 8 + cq;
            float b0 = bias[col], b1 = bias[col + 1];
            #pragma unroll
            for (int hrow = 0; hrow < 2; hrow++) {
                int row = rowBase + warpM * 64 + mf * 16 + rq + hrow * 8;
                size_t off = (size_t)row * N + col;
                float v0 = acc[mf][nf][hrow * 2 + 0] + b0;
                float v1 = acc[mf][nf][hrow * 2 + 1] + b1;
                if (EPI == 1) {
                    float2 rv = *(const float2*)(resid + off);
                    v0 += rv.x; v1 += rv.y;
                }
                if (EPI == 2) { v0 = gelu_f(v0); v1 = gelu_f(v1); }
                if (OF32) *(float2*)(Cf + off) = make_float2(v0, v1);
                if (OB16) {
                    __nv_bfloat162 h;
                    h.x = __float2bfloat16(v0); h.y = __float2bfloat16(v1);
                    *(__nv_bfloat162*)(Cb + off) = h;
                }
            }
        }
    }
}

// ============================================================================
// Attention: K/V staged fp32 in SMEM once per (b,h) block.
// K stored as float4 units, swizzle u^(k&7) (conflict-free per 8-lane phase).
// V read as float2 per lane. Exact fp32 math, bf16 output.
// ============================================================================
#define ASMEM ((2 * NTOK * DH + 8 * DH + 8 * 200) * 4)

__global__ __launch_bounds__(256) void attn_kernel(const float* __restrict__ qkv,
                                                   __nv_bfloat16* __restrict__ out) {
    extern __shared__ float asm_f[];
    float4* Ks4 = (float4*)asm_f;                 // [196][16] swizzled
    float4* Vs4 = (float4*)(asm_f + NTOK * DH);   // [196][16] linear
    float*  qs  = asm_f + 2 * NTOK * DH;          // [8][64]
    float*  ps  = qs + 8 * DH;                    // [8][200]

    int bh = blockIdx.x;
    int b = bh / HEADS, h = bh % HEADS;
    const float* Qb = qkv + (size_t)b * NTOK * QKVDIM + h * DH;
    const float* Kb = Qb + DIM;
    const float* Vb = Qb + 2 * DIM;
    int tid = threadIdx.x;
    int w = tid >> 5, lane = tid & 31;

    for (int idx = tid; idx < NTOK * 16; idx += 256) {
        int k = idx >> 4, u = idx & 15;
        Ks4[k * 16 + (u ^ (k & 7))] = *(const float4*)(Kb + (size_t)k * QKVDIM + u * 4);
        Vs4[idx] = *(const float4*)(Vb + (size_t)k * QKVDIM + u * 4);
    }
    __syncthreads();

    const float4* qs4 = (const float4*)(qs + w * DH);
    const float2* Vs2 = (const float2*)Vs4;

    for (int q = w; q < NTOK; q += 8) {
        for (int d = lane; d < DH; d += 32)
            qs[w * DH + d] = Qb[(size_t)q * QKVDIM + d];
        __syncwarp();

        float sc[7];
        float mx = -1e30f;
        #pragma unroll
        for (int i = 0; i < 7; i++) {
            int k = lane + i * 32;
            float s = -1e30f;
            if (k < NTOK) {
                const float4* kr = Ks4 + k * 16;
                int cx = k & 7;
                float acc = 0.0f;
                #pragma unroll
                for (int u = 0; u < 16; u++) {
                    float4 qv = qs4[u];
                    float4 kv = kr[u ^ cx];
                    acc += qv.x * kv.x + qv.y * kv.y + qv.z * kv.z + qv.w * kv.w;
                }
                s = acc * 0.125f;
            }
            sc[i] = s;
            mx = fmaxf(mx, s);
        }
        #pragma unroll
        for (int o = 16; o; o >>= 1) mx = fmaxf(mx, __shfl_xor_sync(0xffffffffu, mx, o));

        float sum = 0.0f;
        #pragma unroll
        for (int i = 0; i < 7; i++) {
            int k = lane + i * 32;
            float e = (k < NTOK) ? __expf(sc[i] - mx) : 0.0f;
            sc[i] = e;
            sum += e;
        }
        #pragma unroll
        for (int o = 16; o; o >>= 1) sum += __shfl_xor_sync(0xffffffffu, sum, o);
        float inv = 1.0f / sum;

        #pragma unroll
        for (int i = 0; i < 7; i++) {
            int k = lane + i * 32;
            if (k < NTOK) ps[w * 200 + k] = sc[i] * inv;
        }
        __syncwarp();

        // AV: lane owns d = lane*2, lane*2+1
        float a0 = 0.0f, a1 = 0.0f;
        #pragma unroll 4
        for (int k = 0; k < NTOK; k++) {
            float p = ps[w * 200 + k];
            float2 v = Vs2[k * 32 + lane];
            a0 += p * v.x;
            a1 += p * v.y;
        }
        size_t o = ((size_t)b * NTOK + q) * DIM + h * DH + lane * 2;
        __nv_bfloat162 hv;
        hv.x = __float2bfloat16(a0);
        hv.y = __float2bfloat16(a1);
        *(__nv_bfloat162*)(out + o) = hv;
        __syncwarp();
    }
}

// ============================================================================
// Loss
// ============================================================================
__global__ void loss_partial_kernel() {
    double acc = 0.0;
    for (size_t i = (size_t)blockIdx.x * blockDim.x + threadIdx.x;
         i < TOTELEM; i += (size_t)gridDim.x * blockDim.x) {
        int bn = (int)(i / DIM);
        if (g_mask[bn]) acc += fabs((double)g_pred[i] - (double)g_patches[i]);
    }
    __shared__ double red[256];
    red[threadIdx.x] = acc;
    __syncthreads();
    for (int o = 128; o; o >>= 1) {
        if (threadIdx.x < o) red[threadIdx.x] += red[threadIdx.x + o];
        __syncthreads();
    }
    if (threadIdx.x == 0) g_part[blockIdx.x] = red[0];
}

__global__ void loss_final_kernel(float* out) {
    __shared__ double red[256];
    int t = threadIdx.x;
    double a = 0.0;
    for (int i = t; i < 1024; i += 256) a += g_part[i];
    red[t] = a;
    __syncthreads();
    for (int o = 128; o; o >>= 1) { if (t < o) red[t] += red[t + o]; __syncthreads(); }
    if (t == 0) out[0] = (float)(red[0] / (4816896.0 * 98.0));
}

// ============================================================================
// Launch (embed GEMM at launch index 3 = the ncu-captured slot)
// ============================================================================
extern "C" void kernel_launch(void* const* d_in, const int* in_sizes, int n_in,
                              void* d_out, int out_size) {
    const float* img        = (const float*)d_in[0];
    const float* mask_noise = (const float*)d_in[1];
    const float* patch_w    = (const float*)d_in[2];
    const float* patch_b    = (const float*)d_in[3];
    const float* pos_emb    = (const float*)d_in[4];
    const float* mask_token = (const float*)d_in[5];
    const float* ln1_s      = (const float*)d_in[6];
    const float* ln1_b      = (const float*)d_in[7];
    const float* wqkv       = (const float*)d_in[8];
    const float* bqkv       = (const float*)d_in[9];
    const float* wo         = (const float*)d_in[10];
    const float* bo         = (const float*)d_in[11];
    const float* ln2_s      = (const float*)d_in[12];
    const float* ln2_b      = (const float*)d_in[13];
    const float* w1         = (const float*)d_in[14];
    const float* b1         = (const float*)d_in[15];
    const float* w2         = (const float*)d_in[16];
    const float* b2         = (const float*)d_in[17];
    const float* pix_w      = (const float*)d_in[18];
    const float* pix_b      = (const float*)d_in[19];
    float* out = (float*)d_out;

    float *x, *qkv, *pred;
    __nv_bfloat16 *pb, *hb, *ab, *xb, *hidb;
    __nv_bfloat16 *wqkvT, *woT, *w1T, *w2T, *pwT, *pixT;
    cudaGetSymbolAddress((void**)&x,     g_x);
    cudaGetSymbolAddress((void**)&qkv,   g_qkv);
    cudaGetSymbolAddress((void**)&pred,  g_pred);
    cudaGetSymbolAddress((void**)&pb,    g_pb);
    cudaGetSymbolAddress((void**)&hb,    g_hb);
    cudaGetSymbolAddress((void**)&ab,    g_ab);
    cudaGetSymbolAddress((void**)&xb,    g_xb);
    cudaGetSymbolAddress((void**)&hidb,  g_hidb);
    cudaGetSymbolAddress((void**)&wqkvT, g_wqkvT);
    cudaGetSymbolAddress((void**)&woT,   g_woT);
    cudaGetSymbolAddress((void**)&w1T,   g_w1T);
    cudaGetSymbolAddress((void**)&w2T,   g_w2T);
    cudaGetSymbolAddress((void**)&pwT,   g_pwT);
    cudaGetSymbolAddress((void**)&pixT,  g_pixT);

    cudaFuncSetAttribute(gemm_mma<0, true,  false>, cudaFuncAttributeMaxDynamicSharedMemorySize, GSMEM);
    cudaFuncSetAttribute(gemm_mma<1, true,  false>, cudaFuncAttributeMaxDynamicSharedMemorySize, GSMEM);
    cudaFuncSetAttribute(gemm_mma<1, true,  true >, cudaFuncAttributeMaxDynamicSharedMemorySize, GSMEM);
    cudaFuncSetAttribute(gemm_mma<2, false, true >, cudaFuncAttributeMaxDynamicSharedMemorySize, GSMEM);
    cudaFuncSetAttribute(attn_kernel, cudaFuncAttributeMaxDynamicSharedMemorySize, ASMEM);

    int eltBlocks = (int)((TOTELEM + 255) / 256);
    dim3 tb(32, 8);

    // launches 0..2
    patchify_kernel<<<eltBlocks, 256>>>(img);                               // 0
    transpose_w<<<dim3(DIM / 32, DIM / 32), tb>>>(patch_w, pwT, DIM, DIM);  // 1
    topk_kernel<<<BATCH, 256>>>(mask_noise);                                // 2
    // launch 3: profiled embed GEMM
    gemm_mma<0, true, false><<<dim3(DIM / 128, TOKENS / 128), 256, GSMEM>>>(
        pb, pwT, patch_b, nullptr, x, nullptr, DIM, DIM);                   // 3

    finalize_tokens<<<eltBlocks, 256>>>(pos_emb, mask_token);

    // batched weight transposes (z = layer)
    transpose_w<<<dim3(DIM / 32, DIM / 32), tb>>>(pix_w, pixT, DIM, DIM);
    transpose_w<<<dim3(QKVDIM / 32, DIM / 32, DEPTH), tb>>>(wqkv, wqkvT, DIM, QKVDIM);
    transpose_w<<<dim3(DIM / 32, DIM / 32, DEPTH), tb>>>(wo, woT, DIM, DIM);
    transpose_w<<<dim3(MLPDIM / 32, DIM / 32, DEPTH), tb>>>(w1, w1T, DIM, MLPDIM);
    transpose_w<<<dim3(DIM / 32, MLPDIM / 32, DEPTH), tb>>>(w2, w2T, MLPDIM, DIM);

    for (int l = 0; l < DEPTH; l++) {
        ln_kernel<<<TOKENS, 256>>>(x, ln1_s + l * DIM, ln1_b + l * DIM, hb);
        gemm_mma<0, true, false><<<dim3(QKVDIM / 128, TOKENS / 128), 256, GSMEM>>>(
            hb, wqkvT + (size_t)l * QKVDIM * DIM, bqkv + l * QKVDIM, nullptr,
            qkv, nullptr, QKVDIM, DIM);
        attn_kernel<<<BATCH * HEADS, 256, ASMEM>>>(qkv, ab);
        gemm_mma<1, true, false><<<dim3(DIM / 128, TOKENS / 128), 256, GSMEM>>>(
            ab, woT + (size_t)l * DIM * DIM, bo + l * DIM, x,
            x, nullptr, DIM, DIM);
        ln_kernel<<<TOKENS, 256>>>(x, ln2_s + l * DIM, ln2_b + l * DIM, hb);
        gemm_mma<2, false, true><<<dim3(MLPDIM / 128, TOKENS / 128), 256, GSMEM>>>(
            hb, w1T + (size_t)l * MLPDIM * DIM, b1 + l * MLPDIM, nullptr,
            nullptr, hidb, MLPDIM, DIM);
        if (l < DEPTH - 1) {
            gemm_mma<1, true, false><<<dim3(DIM / 128, TOKENS / 128), 256, GSMEM>>>(
                hidb, w2T + (size_t)l * DIM * MLPDIM, b2 + l * DIM, x,
                x, nullptr, DIM, MLPDIM);
        } else {
            gemm_mma<1, true, true><<<dim3(DIM / 128, TOKENS / 128), 256, GSMEM>>>(
                hidb, w2T + (size_t)l * DIM * MLPDIM, b2 + l * DIM, x,
                x, xb, DIM, MLPDIM);
        }
    }

    // pixel head
    gemm_mma<0, true, false><<<dim3(DIM / 128, TOKENS / 128), 256, GSMEM>>>(
        xb, pixT, pix_b, nullptr, pred, nullptr, DIM, DIM);

    loss_partial_kernel<<<1024, 256>>>();
    loss_final_kernel<<<1, 256>>>(out);
}

// round 14
// speedup vs baseline: 1.4305x; 1.2494x over previous
#include <cuda_runtime.h>
#include <cuda_bf16.h>
#include <math.h>
#include <stdint.h>

// ============================================================================
// SimMIM forward, Round 13:
//  - Attention: 4-q-per-warp blocking, conflict-free K swizzle (u^((k>>1)&15)),
//    k-paired V float4 layout, register-resident p via shfl. FMA-bound now.
//  - LN: warp-per-row, barrier-free, float4 I/O.
//  - finalize_tokens fused into embed GEMM epilogue (EPI=3).
//  - GEMM: R13 config (128x128, BK=64, 3-stage, 2 CTAs/SM, B via ldm_x4).
// ============================================================================

#define BATCH   64
#define NTOK    196
#define DIM     768
#define QKVDIM  2304
#define MLPDIM  3072
#define HEADS   12
#define DH      64
#define DEPTH   6
#define NMASK   98
#define TOKENS  (BATCH * NTOK)          // 12544 = 98*128
#define TOTELEM ((size_t)TOKENS * DIM)

// ---- fp32 scratch ----
__device__ float  g_patches[TOKENS * DIM];
__device__ float  g_x      [TOKENS * DIM];
__device__ float  g_qkv    [TOKENS * QKVDIM];
__device__ float  g_pred   [TOKENS * DIM];
__device__ int    g_mask   [BATCH * NTOK];
__device__ double g_part   [1024];

// ---- bf16 scratch ----
__device__ __nv_bfloat16 g_pb  [TOKENS * DIM];
__device__ __nv_bfloat16 g_hb  [TOKENS * DIM];
__device__ __nv_bfloat16 g_ab  [TOKENS * DIM];
__device__ __nv_bfloat16 g_xb  [TOKENS * DIM];
__device__ __nv_bfloat16 g_hidb[(size_t)TOKENS * MLPDIM];

// ---- bf16 transposed weights [N,K] ----
__device__ __nv_bfloat16 g_wqkvT[DEPTH * QKVDIM * DIM];
__device__ __nv_bfloat16 g_woT  [DEPTH * DIM * DIM];
__device__ __nv_bfloat16 g_w1T  [DEPTH * MLPDIM * DIM];
__device__ __nv_bfloat16 g_w2T  [(size_t)DEPTH * DIM * MLPDIM];
__device__ __nv_bfloat16 g_pwT  [DIM * DIM];
__device__ __nv_bfloat16 g_pixT [DIM * DIM];

// ============================================================================
// PTX helpers
// ============================================================================
__device__ __forceinline__ uint32_t smem_u32(const void* p) {
    uint32_t a;
    asm("{ .reg .u64 t; cvta.to.shared.u64 t, %1; cvt.u32.u64 %0, t; }"
        : "=r"(a) : "l"(p));
    return a;
}
__device__ __forceinline__ void cp_async16(uint32_t dst, const void* src) {
    asm volatile("cp.async.cg.shared.global [%0], [%1], 16;" :: "r"(dst), "l"(src));
}
__device__ __forceinline__ void cp_commit() {
    asm volatile("cp.async.commit_group;");
}
__device__ __forceinline__ void ldm_x4(uint32_t* r, uint32_t addr) {
    asm volatile("ldmatrix.sync.aligned.m8n8.x4.shared.b16 {%0,%1,%2,%3}, [%4];"
                 : "=r"(r[0]), "=r"(r[1]), "=r"(r[2]), "=r"(r[3]) : "r"(addr));
}
__device__ __forceinline__ void mma16816(float* d, const uint32_t* a, const uint32_t* b) {
    asm volatile(
        "mma.sync.aligned.m16n8k16.row.col.f32.bf16.bf16.f32 "
        "{%0,%1,%2,%3}, {%4,%5,%6,%7}, {%8,%9}, {%0,%1,%2,%3};"
        : "+f"(d[0]), "+f"(d[1]), "+f"(d[2]), "+f"(d[3])
        : "r"(a[0]), "r"(a[1]), "r"(a[2]), "r"(a[3]), "r"(b[0]), "r"(b[1]));
}

// SMEM GEMM tile: 128 rows x 64 bf16. seg' = seg ^ (row & 7); kk flips ^(kk<<5).
__device__ __forceinline__ uint32_t swz64(int row, int seg) {
    return (uint32_t)(row * 128 + ((seg ^ (row & 7)) << 4));
}

// ============================================================================
// small kernels
// ============================================================================
__global__ void patchify_kernel(const float* __restrict__ img) {
    size_t i = (size_t)blockIdx.x * blockDim.x + threadIdx.x;
    if (i >= TOTELEM) return;
    int d  = (int)(i % DIM);
    int n  = (int)((i / DIM) % NTOK);
    int b  = (int)(i / ((size_t)DIM * NTOK));
    int gi = n / 14, gj = n % 14;
    int pi = d / 48; int rem = d % 48; int pj = rem / 3; int c = rem % 3;
    size_t src = (((size_t)b * 224 + gi * 16 + pi) * 224 + (gj * 16 + pj)) * 3 + c;
    float v = img[src];
    g_patches[i] = v;
    g_pb[i] = __float2bfloat16(v);
}

__global__ void topk_kernel(const float* __restrict__ noise) {
    int b = blockIdx.x;
    __shared__ float v[NTOK];
    int t = threadIdx.x;
    if (t < NTOK) v[t] = noise[b * NTOK + t];
    __syncthreads();
    if (t < NTOK) {
        float mv = v[t];
        int rank = 0;
        for (int j = 0; j < NTOK; j++)
            rank += (v[j] > mv) || (v[j] == mv && j < t);
        g_mask[b * NTOK + t] = (rank < NMASK) ? 1 : 0;
    }
}

// warp-per-row LayerNorm -> bf16 (no block barriers)
__global__ __launch_bounds__(256) void ln_kernel(const float* __restrict__ x,
                                                 const float* __restrict__ s,
                                                 const float* __restrict__ bp,
                                                 __nv_bfloat16* __restrict__ out) {
    int row = blockIdx.x * 8 + (threadIdx.x >> 5);
    int lane = threadIdx.x & 31;
    const float4* xr = (const float4*)(x + (size_t)row * DIM);
    float4 v[6];
    float s1 = 0.0f, s2 = 0.0f;
    #pragma unroll
    for (int i = 0; i < 6; i++) {
        v[i] = xr[lane + 32 * i];
        s1 += v[i].x + v[i].y + v[i].z + v[i].w;
        s2 += v[i].x * v[i].x + v[i].y * v[i].y + v[i].z * v[i].z + v[i].w * v[i].w;
    }
    #pragma unroll
    for (int o = 16; o; o >>= 1) {
        s1 += __shfl_xor_sync(0xffffffffu, s1, o);
        s2 += __shfl_xor_sync(0xffffffffu, s2, o);
    }
    float mean = s1 * (1.0f / DIM);
    float var  = s2 * (1.0f / DIM) - mean * mean;
    float rstd = rsqrtf(var + 1e-5f);
    const float4* sv = (const float4*)s;
    const float4* bv = (const float4*)bp;
    #pragma unroll
    for (int i = 0; i < 6; i++) {
        float4 sf = sv[lane + 32 * i];
        float4 bf = bv[lane + 32 * i];
        float o0 = (v[i].x - mean) * rstd * sf.x + bf.x;
        float o1 = (v[i].y - mean) * rstd * sf.y + bf.y;
        float o2 = (v[i].z - mean) * rstd * sf.z + bf.z;
        float o3 = (v[i].w - mean) * rstd * sf.w + bf.w;
        __nv_bfloat162 ha, hb;
        ha.x = __float2bfloat16(o0); ha.y = __float2bfloat16(o1);
        hb.x = __float2bfloat16(o2); hb.y = __float2bfloat16(o3);
        uint2 u;
        u.x = *(uint32_t*)&ha; u.y = *(uint32_t*)&hb;
        *(uint2*)(out + (size_t)row * DIM + (lane + 32 * i) * 4) = u;
    }
}

// W[K,N] fp32 -> Wt[N,K] bf16 (z = layer)
__global__ void transpose_w(const float* __restrict__ W,
                            __nv_bfloat16* __restrict__ Wt, int K, int N) {
    __shared__ float t[32][33];
    W  += (size_t)blockIdx.z * K * N;
    Wt += (size_t)blockIdx.z * N * K;
    int bn = blockIdx.x * 32, bk = blockIdx.y * 32;
    int tx = threadIdx.x, ty = threadIdx.y;
    #pragma unroll
    for (int j = 0; j < 32; j += 8)
        t[ty + j][tx] = W[(size_t)(bk + ty + j) * N + bn + tx];
    __syncthreads();
    #pragma unroll
    for (int j = 0; j < 32; j += 8)
        Wt[(size_t)(bn + ty + j) * K + bk + tx] = __float2bfloat16(t[tx][ty + j]);
}

__device__ __forceinline__ float gelu_f(float x) {
    float x3 = x * x * x;
    return 0.5f * x * (1.0f + tanhf(0.7978845608028654f * (x + 0.044715f * x3)));
}

// ============================================================================
// bf16 tensor-core GEMM: C[M,N] = epi(A[M,K] @ Bt[N,K]^T + bias)
// EPI: 0=bias, 1=bias+resid, 2=gelu(bias), 3=bias+posemb/mask (embed+finalize)
// ============================================================================
#define GSTAGE 32768
#define GSMEM  (3 * GSTAGE)

template<int EPI, bool OF32, bool OB16>
__global__ __launch_bounds__(256) void gemm_mma(
    const __nv_bfloat16* __restrict__ A,
    const __nv_bfloat16* __restrict__ Bt,
    const float* __restrict__ bias,
    const float* __restrict__ resid,
    float* __restrict__ Cf,
    __nv_bfloat16* __restrict__ Cb,
    int N, int K,
    const float* __restrict__ pe,
    const float* __restrict__ mtok)
{
    extern __shared__ __align__(16) char smem[];
    const uint32_t sbase = smem_u32(smem);
    const int tid = threadIdx.x;
    const int wid = tid >> 5, lane = tid & 31;
    const int warpM = wid >> 2;
    const int warpN = wid & 3;
    const int rowBase = blockIdx.y * 128;
    const int colBase = blockIdx.x * 128;
    const int KCH = K >> 6;

    const int lrow = tid >> 1;
    const int lseg = (tid & 1) * 4;
    const __nv_bfloat16* aSrc = A  + (size_t)(rowBase + lrow) * K + lseg * 8;
    const __nv_bfloat16* bSrc = Bt + (size_t)(colBase + lrow) * K + lseg * 8;
    uint32_t dOff[4];
    #pragma unroll
    for (int i = 0; i < 4; i++) dOff[i] = swz64(lrow, lseg + i);

    uint32_t offA[4], offB[2];
    #pragma unroll
    for (int mf = 0; mf < 4; mf++)
        offA[mf] = swz64(warpM * 64 + mf * 16 + (lane & 15), (lane >> 4));
    #pragma unroll
    for (int p = 0; p < 2; p++)
        offB[p] = 16384u + swz64(warpN * 32 + p * 16 + (lane & 7) + ((lane >> 4) << 3),
                                 (lane >> 3) & 1);

    float acc[4][4][4];
    #pragma unroll
    for (int i = 0; i < 4; i++)
        #pragma unroll
        for (int j = 0; j < 4; j++)
            #pragma unroll
            for (int e = 0; e < 4; e++) acc[i][j][e] = 0.0f;

    auto stage_load = [&](int kc, int s) {
        uint32_t st = sbase + (uint32_t)s * GSTAGE;
        const __nv_bfloat16* a = aSrc + kc * 64;
        const __nv_bfloat16* b = bSrc + kc * 64;
        #pragma unroll
        for (int i = 0; i < 4; i++) {
            cp_async16(st + dOff[i], a + i * 8);
            cp_async16(st + 16384 + dOff[i], b + i * 8);
        }
        cp_commit();
    };

    stage_load(0, 0);
    if (KCH > 1) stage_load(1, 1);

    int sIdx = 0;
    for (int c = 0; c < KCH; c++) {
        if (c + 1 < KCH) asm volatile("cp.async.wait_group 1;");
        else             asm volatile("cp.async.wait_group 0;");
        __syncthreads();

        if (c + 2 < KCH) {
            int ns = sIdx + 2; if (ns >= 3) ns -= 3;
            stage_load(c + 2, ns);
        }

        uint32_t base = sbase + (uint32_t)sIdx * GSTAGE;
        #pragma unroll
        for (int kk = 0; kk < 4; kk++) {
            uint32_t x = (uint32_t)kk << 5;
            uint32_t afr[4][4];
            #pragma unroll
            for (int mf = 0; mf < 4; mf++) ldm_x4(afr[mf], base + (offA[mf] ^ x));
            uint32_t bfr[4][2];
            #pragma unroll
            for (int p = 0; p < 2; p++) {
                uint32_t r[4];
                ldm_x4(r, base + (offB[p] ^ x));
                bfr[p * 2][0] = r[0]; bfr[p * 2][1] = r[1];
                bfr[p * 2 + 1][0] = r[2]; bfr[p * 2 + 1][1] = r[3];
            }
            #pragma unroll
            for (int mf = 0; mf < 4; mf++)
                #pragma unroll
                for (int nf = 0; nf < 4; nf++)
                    mma16816(acc[mf][nf], afr[mf], bfr[nf]);
        }
        sIdx++; if (sIdx == 3) sIdx = 0;
    }

    // ---- epilogue straight from registers ----
    const int rq = lane >> 2;
    const int cq = (lane & 3) * 2;
    #pragma unroll
    for (int mf = 0; mf < 4; mf++) {
        #pragma unroll
        for (int nf = 0; nf < 4; nf++) {
            int col = colBase + warpN * 32 + nf * 8 + cq;
            float b0 = bias[col], b1 = bias[col + 1];
            #pragma unroll
            for (int hrow = 0; hrow < 2; hrow++) {
                int row = rowBase + warpM * 64 + mf * 16 + rq + hrow * 8;
                size_t off = (size_t)row * N + col;
                float v0 = acc[mf][nf][hrow * 2 + 0] + b0;
                float v1 = acc[mf][nf][hrow * 2 + 1] + b1;
                if (EPI == 1) {
                    float2 rv = *(const float2*)(resid + off);
                    v0 += rv.x; v1 += rv.y;
                }
                if (EPI == 2) { v0 = gelu_f(v0); v1 = gelu_f(v1); }
                if (EPI == 3) {
                    int n = row % NTOK;
                    float2 pev = *(const float2*)(pe + (size_t)(n + 1) * DIM + col);
                    if (g_mask[row]) {
                        float2 mt = *(const float2*)(mtok + col);
                        v0 = mt.x + pev.x; v1 = mt.y + pev.y;
                    } else {
                        v0 += pev.x; v1 += pev.y;
                    }
                }
                if (OF32) *(float2*)(Cf + off) = make_float2(v0, v1);
                if (OB16) {
                    __nv_bfloat162 h;
                    h.x = __float2bfloat16(v0); h.y = __float2bfloat16(v1);
                    *(__nv_bfloat162*)(Cb + off) = h;
                }
            }
        }
    }
}

// ============================================================================
// Attention: 4 q per warp; K float4 swizzle u^((k>>1)&15) (conflict-free over
// 32 rows); V stored k-paired float4; p in registers via shfl. fp32 exact.
// SMEM: K 49KB + Vp 49KB + q 8KB = 106KB -> 2 blocks/SM.
// ============================================================================
#define ASMEM ((NTOK * DH + NTOK * DH + 8 * 4 * DH) * 4)

__global__ __launch_bounds__(256) void attn_kernel(const float* __restrict__ qkv,
                                                   __nv_bfloat16* __restrict__ out) {
    extern __shared__ float asm_f[];
    float4* Ks4 = (float4*)asm_f;                     // [196][16], swizzled
    float4* Vp4 = (float4*)(asm_f + NTOK * DH);       // [98][32] k-paired
    float4* qsm = (float4*)(asm_f + 2 * NTOK * DH);   // [8][4][16]

    int bh = blockIdx.x;
    int b = bh / HEADS, h = bh % HEADS;
    const float* Qb = qkv + (size_t)b * NTOK * QKVDIM + h * DH;
    const float* Kb = Qb + DIM;
    const float* Vb = Qb + 2 * DIM;
    int tid = threadIdx.x;
    int w = tid >> 5, lane = tid & 31;

    for (int idx = tid; idx < NTOK * 16; idx += 256) {
        int k = idx >> 4, u = idx & 15;
        Ks4[k * 16 + (u ^ ((k >> 1) & 15))] =
            *(const float4*)(Kb + (size_t)k * QKVDIM + u * 4);
    }
    for (int idx = tid; idx < 98 * 32; idx += 256) {
        int kp = idx >> 5, l = idx & 31;
        float2 a = *(const float2*)(Vb + (size_t)(2 * kp)     * QKVDIM + 2 * l);
        float2 c = *(const float2*)(Vb + (size_t)(2 * kp + 1) * QKVDIM + 2 * l);
        Vp4[idx] = make_float4(a.x, a.y, c.x, c.y);
    }
    __syncthreads();

    for (int ch = w; ch < 49; ch += 8) {
        // stage 4 q rows
        __syncwarp();
        #pragma unroll
        for (int t = 0; t < 2; t++) {
            int e = lane + t * 32;          // 0..63
            int qq = e >> 4, u = e & 15;
            qsm[(w * 4 + qq) * 16 + u] =
                *(const float4*)(Qb + (size_t)(ch * 4 + qq) * QKVDIM + u * 4);
        }
        __syncwarp();

        // ---- QK: sc[qq][i] = q[qq] . k(lane+32i) ----
        float sc[4][7];
        #pragma unroll
        for (int qq = 0; qq < 4; qq++)
            #pragma unroll
            for (int i = 0; i < 7; i++) sc[qq][i] = 0.0f;

        #pragma unroll
        for (int u = 0; u < 16; u++) {
            float4 q0 = qsm[(w * 4 + 0) * 16 + u];
            float4 q1 = qsm[(w * 4 + 1) * 16 + u];
            float4 q2 = qsm[(w * 4 + 2) * 16 + u];
            float4 q3 = qsm[(w * 4 + 3) * 16 + u];
            #pragma unroll
            for (int i = 0; i < 7; i++) {
                int k = lane + 32 * i;
                int ks = (k < NTOK) ? k : 0;
                float4 kv = Ks4[ks * 16 + (u ^ ((ks >> 1) & 15))];
                sc[0][i] += q0.x * kv.x + q0.y * kv.y + q0.z * kv.z + q0.w * kv.w;
                sc[1][i] += q1.x * kv.x + q1.y * kv.y + q1.z * kv.z + q1.w * kv.w;
                sc[2][i] += q2.x * kv.x + q2.y * kv.y + q2.z * kv.z + q2.w * kv.w;
                sc[3][i] += q3.x * kv.x + q3.y * kv.y + q3.z * kv.z + q3.w * kv.w;
            }
        }

        // ---- softmax per qq (p stays in sc regs) ----
        #pragma unroll
        for (int qq = 0; qq < 4; qq++) {
            float mx = -1e30f;
            #pragma unroll
            for (int i = 0; i < 7; i++) {
                int k = lane + 32 * i;
                float s = (k < NTOK) ? sc[qq][i] * 0.125f : -1e30f;
                sc[qq][i] = s;
                mx = fmaxf(mx, s);
            }
            #pragma unroll
            for (int o = 16; o; o >>= 1)
                mx = fmaxf(mx, __shfl_xor_sync(0xffffffffu, mx, o));
            float sum = 0.0f;
            #pragma unroll
            for (int i = 0; i < 7; i++) {
                int k = lane + 32 * i;
                float e = (k < NTOK) ? __expf(sc[qq][i] - mx) : 0.0f;
                sc[qq][i] = e;
                sum += e;
            }
            #pragma unroll
            for (int o = 16; o; o >>= 1)
                sum += __shfl_xor_sync(0xffffffffu, sum, o);
            float inv = 1.0f / sum;
            #pragma unroll
            for (int i = 0; i < 7; i++) sc[qq][i] *= inv;
        }

        // ---- AV: lane owns d = 2*lane, 2*lane+1 ----
        float a0[4] = {0, 0, 0, 0}, a1[4] = {0, 0, 0, 0};
        #pragma unroll
        for (int i = 0; i < 7; i++) {
            #pragma unroll
            for (int j = 0; j < 16; j++) {
                if (i * 16 + j >= 98) break;        // compile-time resolved
                int kp = i * 16 + j;
                float4 v = Vp4[kp * 32 + lane];
                #pragma unroll
                for (int qq = 0; qq < 4; qq++) {
                    float p0 = __shfl_sync(0xffffffffu, sc[qq][i], 2 * j);
                    float p1 = __shfl_sync(0xffffffffu, sc[qq][i], 2 * j + 1);
                    a0[qq] += p0 * v.x + p1 * v.z;
                    a1[qq] += p0 * v.y + p1 * v.w;
                }
            }
        }

        #pragma unroll
        for (int qq = 0; qq < 4; qq++) {
            size_t o = ((size_t)b * NTOK + ch * 4 + qq) * DIM + h * DH + 2 * lane;
            __nv_bfloat162 hv;
            hv.x = __float2bfloat16(a0[qq]);
            hv.y = __float2bfloat16(a1[qq]);
            *(__nv_bfloat162*)(out + o) = hv;
        }
    }
}

// ============================================================================
// Loss
// ============================================================================
__global__ void loss_partial_kernel() {
    double acc = 0.0;
    for (size_t i = (size_t)blockIdx.x * blockDim.x + threadIdx.x;
         i < TOTELEM; i += (size_t)gridDim.x * blockDim.x) {
        int bn = (int)(i / DIM);
        if (g_mask[bn]) acc += fabs((double)g_pred[i] - (double)g_patches[i]);
    }
    __shared__ double red[256];
    red[threadIdx.x] = acc;
    __syncthreads();
    for (int o = 128; o; o >>= 1) {
        if (threadIdx.x < o) red[threadIdx.x] += red[threadIdx.x + o];
        __syncthreads();
    }
    if (threadIdx.x == 0) g_part[blockIdx.x] = red[0];
}

__global__ void loss_final_kernel(float* out) {
    __shared__ double red[256];
    int t = threadIdx.x;
    double a = 0.0;
    for (int i = t; i < 1024; i += 256) a += g_part[i];
    red[t] = a;
    __syncthreads();
    for (int o = 128; o; o >>= 1) { if (t < o) red[t] += red[t + o]; __syncthreads(); }
    if (t == 0) out[0] = (float)(red[0] / (4816896.0 * 98.0));
}

// ============================================================================
// Launch (embed GEMM at launch index 3 = the ncu-captured slot)
// ============================================================================
extern "C" void kernel_launch(void* const* d_in, const int* in_sizes, int n_in,
                              void* d_out, int out_size) {
    const float* img        = (const float*)d_in[0];
    const float* mask_noise = (const float*)d_in[1];
    const float* patch_w    = (const float*)d_in[2];
    const float* patch_b    = (const float*)d_in[3];
    const float* pos_emb    = (const float*)d_in[4];
    const float* mask_token = (const float*)d_in[5];
    const float* ln1_s      = (const float*)d_in[6];
    const float* ln1_b      = (const float*)d_in[7];
    const float* wqkv       = (const float*)d_in[8];
    const float* bqkv       = (const float*)d_in[9];
    const float* wo         = (const float*)d_in[10];
    const float* bo         = (const float*)d_in[11];
    const float* ln2_s      = (const float*)d_in[12];
    const float* ln2_b      = (const float*)d_in[13];
    const float* w1         = (const float*)d_in[14];
    const float* b1         = (const float*)d_in[15];
    const float* w2         = (const float*)d_in[16];
    const float* b2         = (const float*)d_in[17];
    const float* pix_w      = (const float*)d_in[18];
    const float* pix_b      = (const float*)d_in[19];
    float* out = (float*)d_out;

    float *x, *qkv, *pred;
    __nv_bfloat16 *pb, *hb, *ab, *xb, *hidb;
    __nv_bfloat16 *wqkvT, *woT, *w1T, *w2T, *pwT, *pixT;
    cudaGetSymbolAddress((void**)&x,     g_x);
    cudaGetSymbolAddress((void**)&qkv,   g_qkv);
    cudaGetSymbolAddress((void**)&pred,  g_pred);
    cudaGetSymbolAddress((void**)&pb,    g_pb);
    cudaGetSymbolAddress((void**)&hb,    g_hb);
    cudaGetSymbolAddress((void**)&ab,    g_ab);
    cudaGetSymbolAddress((void**)&xb,    g_xb);
    cudaGetSymbolAddress((void**)&hidb,  g_hidb);
    cudaGetSymbolAddress((void**)&wqkvT, g_wqkvT);
    cudaGetSymbolAddress((void**)&woT,   g_woT);
    cudaGetSymbolAddress((void**)&w1T,   g_w1T);
    cudaGetSymbolAddress((void**)&w2T,   g_w2T);
    cudaGetSymbolAddress((void**)&pwT,   g_pwT);
    cudaGetSymbolAddress((void**)&pixT,  g_pixT);

    cudaFuncSetAttribute(gemm_mma<0, true,  false>, cudaFuncAttributeMaxDynamicSharedMemorySize, GSMEM);
    cudaFuncSetAttribute(gemm_mma<1, true,  false>, cudaFuncAttributeMaxDynamicSharedMemorySize, GSMEM);
    cudaFuncSetAttribute(gemm_mma<1, true,  true >, cudaFuncAttributeMaxDynamicSharedMemorySize, GSMEM);
    cudaFuncSetAttribute(gemm_mma<2, false, true >, cudaFuncAttributeMaxDynamicSharedMemorySize, GSMEM);
    cudaFuncSetAttribute(gemm_mma<3, true,  false>, cudaFuncAttributeMaxDynamicSharedMemorySize, GSMEM);
    cudaFuncSetAttribute(attn_kernel, cudaFuncAttributeMaxDynamicSharedMemorySize, ASMEM);

    int eltBlocks = (int)((TOTELEM + 255) / 256);
    dim3 tb(32, 8);

    // launches 0..2
    patchify_kernel<<<eltBlocks, 256>>>(img);                               // 0
    transpose_w<<<dim3(DIM / 32, DIM / 32), tb>>>(patch_w, pwT, DIM, DIM);  // 1
    topk_kernel<<<BATCH, 256>>>(mask_noise);                                // 2
    // launch 3 (profiled): embed GEMM with fused finalize (pos_emb + mask)
    gemm_mma<3, true, false><<<dim3(DIM / 128, TOKENS / 128), 256, GSMEM>>>(
        pb, pwT, patch_b, nullptr, x, nullptr, DIM, DIM,
        pos_emb, mask_token);                                               // 3

    // batched weight transposes (z = layer)
    transpose_w<<<dim3(DIM / 32, DIM / 32), tb>>>(pix_w, pixT, DIM, DIM);
    transpose_w<<<dim3(QKVDIM / 32, DIM / 32, DEPTH), tb>>>(wqkv, wqkvT, DIM, QKVDIM);
    transpose_w<<<dim3(DIM / 32, DIM / 32, DEPTH), tb>>>(wo, woT, DIM, DIM);
    transpose_w<<<dim3(MLPDIM / 32, DIM / 32, DEPTH), tb>>>(w1, w1T, DIM, MLPDIM);
    transpose_w<<<dim3(DIM / 32, MLPDIM / 32, DEPTH), tb>>>(w2, w2T, MLPDIM, DIM);

    for (int l = 0; l < DEPTH; l++) {
        ln_kernel<<<TOKENS / 8, 256>>>(x, ln1_s + l * DIM, ln1_b + l * DIM, hb);
        gemm_mma<0, true, false><<<dim3(QKVDIM / 128, TOKENS / 128), 256, GSMEM>>>(
            hb, wqkvT + (size_t)l * QKVDIM * DIM, bqkv + l * QKVDIM, nullptr,
            qkv, nullptr, QKVDIM, DIM, nullptr, nullptr);
        attn_kernel<<<BATCH * HEADS, 256, ASMEM>>>(qkv, ab);
        gemm_mma<1, true, false><<<dim3(DIM / 128, TOKENS / 128), 256, GSMEM>>>(
            ab, woT + (size_t)l * DIM * DIM, bo + l * DIM, x,
            x, nullptr, DIM, DIM, nullptr, nullptr);
        ln_kernel<<<TOKENS / 8, 256>>>(x, ln2_s + l * DIM, ln2_b + l * DIM, hb);
        gemm_mma<2, false, true><<<dim3(MLPDIM / 128, TOKENS / 128), 256, GSMEM>>>(
            hb, w1T + (size_t)l * MLPDIM * DIM, b1 + l * MLPDIM, nullptr,
            nullptr, hidb, MLPDIM, DIM, nullptr, nullptr);
        if (l < DEPTH - 1) {
            gemm_mma<1, true, false><<<dim3(DIM / 128, TOKENS / 128), 256, GSMEM>>>(
                hidb, w2T + (size_t)l * DIM * MLPDIM, b2 + l * DIM, x,
                x, nullptr, DIM, MLPDIM, nullptr, nullptr);
        } else {
            gemm_mma<1, true, true><<<dim3(DIM / 128, TOKENS / 128), 256, GSMEM>>>(
                hidb, w2T + (size_t)l * DIM * MLPDIM, b2 + l * DIM, x,
                x, xb, DIM, MLPDIM, nullptr, nullptr);
        }
    }

    // pixel head
    gemm_mma<0, true, false><<<dim3(DIM / 128, TOKENS / 128), 256, GSMEM>>>(
        xb, pixT, pix_b, nullptr, pred, nullptr, DIM, DIM, nullptr, nullptr);

    loss_partial_kernel<<<1024, 256>>>();
    loss_final_kernel<<<1, 256>>>(out);
}

// round 16
// speedup vs baseline: 1.7129x; 1.1974x over previous
#include <cuda_runtime.h>
#include <cuda_bf16.h>
#include <math.h>
#include <stdint.h>

// ============================================================================
// SimMIM forward, Round 14:
//  - Attention moved to tensor cores (mma.sync bf16): S=QK^T and O=PV both
//    via the GEMM-proven fragment addressing; softmax fp32 in SMEM, masked.
//  - Everything else identical to R14 (GEMM 128x128 BK=64 3-stage, warp-LN,
//    fused embed finalize, batched transposes).
// ============================================================================

#define BATCH   64
#define NTOK    196
#define DIM     768
#define QKVDIM  2304
#define MLPDIM  3072
#define HEADS   12
#define DH      64
#define DEPTH   6
#define NMASK   98
#define TOKENS  (BATCH * NTOK)          // 12544 = 98*128
#define TOTELEM ((size_t)TOKENS * DIM)

// ---- fp32 scratch ----
__device__ float  g_patches[TOKENS * DIM];
__device__ float  g_x      [TOKENS * DIM];
__device__ float  g_qkv    [TOKENS * QKVDIM];
__device__ float  g_pred   [TOKENS * DIM];
__device__ int    g_mask   [BATCH * NTOK];
__device__ double g_part   [1024];

// ---- bf16 scratch ----
__device__ __nv_bfloat16 g_pb  [TOKENS * DIM];
__device__ __nv_bfloat16 g_hb  [TOKENS * DIM];
__device__ __nv_bfloat16 g_ab  [TOKENS * DIM];
__device__ __nv_bfloat16 g_xb  [TOKENS * DIM];
__device__ __nv_bfloat16 g_hidb[(size_t)TOKENS * MLPDIM];

// ---- bf16 transposed weights [N,K] ----
__device__ __nv_bfloat16 g_wqkvT[DEPTH * QKVDIM * DIM];
__device__ __nv_bfloat16 g_woT  [DEPTH * DIM * DIM];
__device__ __nv_bfloat16 g_w1T  [DEPTH * MLPDIM * DIM];
__device__ __nv_bfloat16 g_w2T  [(size_t)DEPTH * DIM * MLPDIM];
__device__ __nv_bfloat16 g_pwT  [DIM * DIM];
__device__ __nv_bfloat16 g_pixT [DIM * DIM];

// ============================================================================
// PTX helpers
// ============================================================================
__device__ __forceinline__ uint32_t smem_u32(const void* p) {
    uint32_t a;
    asm("{ .reg .u64 t; cvta.to.shared.u64 t, %1; cvt.u32.u64 %0, t; }"
        : "=r"(a) : "l"(p));
    return a;
}
__device__ __forceinline__ void cp_async16(uint32_t dst, const void* src) {
    asm volatile("cp.async.cg.shared.global [%0], [%1], 16;" :: "r"(dst), "l"(src));
}
__device__ __forceinline__ void cp_commit() {
    asm volatile("cp.async.commit_group;");
}
__device__ __forceinline__ void ldm_x4(uint32_t* r, uint32_t addr) {
    asm volatile("ldmatrix.sync.aligned.m8n8.x4.shared.b16 {%0,%1,%2,%3}, [%4];"
                 : "=r"(r[0]), "=r"(r[1]), "=r"(r[2]), "=r"(r[3]) : "r"(addr));
}
__device__ __forceinline__ void ldm_x2(uint32_t* r, uint32_t addr) {
    asm volatile("ldmatrix.sync.aligned.m8n8.x2.shared.b16 {%0,%1}, [%2];"
                 : "=r"(r[0]), "=r"(r[1]) : "r"(addr));
}
__device__ __forceinline__ void mma16816(float* d, const uint32_t* a, const uint32_t* b) {
    asm volatile(
        "mma.sync.aligned.m16n8k16.row.col.f32.bf16.bf16.f32 "
        "{%0,%1,%2,%3}, {%4,%5,%6,%7}, {%8,%9}, {%0,%1,%2,%3};"
        : "+f"(d[0]), "+f"(d[1]), "+f"(d[2]), "+f"(d[3])
        : "r"(a[0]), "r"(a[1]), "r"(a[2]), "r"(a[3]), "r"(b[0]), "r"(b[1]));
}

// SMEM GEMM tile: 128 rows x 64 bf16. seg' = seg ^ (row & 7); kk flips ^(kk<<5).
__device__ __forceinline__ uint32_t swz64(int row, int seg) {
    return (uint32_t)(row * 128 + ((seg ^ (row & 7)) << 4));
}
// generic seg swizzle for 512B-row layouts (keeps seg's high bits)
__device__ __forceinline__ int segswz(int row, int seg) {
    return (seg & ~7) | ((seg ^ row) & 7);
}
__device__ __forceinline__ uint4 pack8bf(const float* s) {
    float4 x = *(const float4*)s, y = *(const float4*)(s + 4);
    __nv_bfloat162 a, b, c, d;
    a.x = __float2bfloat16(x.x); a.y = __float2bfloat16(x.y);
    b.x = __float2bfloat16(x.z); b.y = __float2bfloat16(x.w);
    c.x = __float2bfloat16(y.x); c.y = __float2bfloat16(y.y);
    d.x = __float2bfloat16(y.z); d.y = __float2bfloat16(y.w);
    uint4 u;
    u.x = *(uint32_t*)&a; u.y = *(uint32_t*)&b;
    u.z = *(uint32_t*)&c; u.w = *(uint32_t*)&d;
    return u;
}

// ============================================================================
// small kernels
// ============================================================================
__global__ void patchify_kernel(const float* __restrict__ img) {
    size_t i = (size_t)blockIdx.x * blockDim.x + threadIdx.x;
    if (i >= TOTELEM) return;
    int d  = (int)(i % DIM);
    int n  = (int)((i / DIM) % NTOK);
    int b  = (int)(i / ((size_t)DIM * NTOK));
    int gi = n / 14, gj = n % 14;
    int pi = d / 48; int rem = d % 48; int pj = rem / 3; int c = rem % 3;
    size_t src = (((size_t)b * 224 + gi * 16 + pi) * 224 + (gj * 16 + pj)) * 3 + c;
    float v = img[src];
    g_patches[i] = v;
    g_pb[i] = __float2bfloat16(v);
}

__global__ void topk_kernel(const float* __restrict__ noise) {
    int b = blockIdx.x;
    __shared__ float v[NTOK];
    int t = threadIdx.x;
    if (t < NTOK) v[t] = noise[b * NTOK + t];
    __syncthreads();
    if (t < NTOK) {
        float mv = v[t];
        int rank = 0;
        for (int j = 0; j < NTOK; j++)
            rank += (v[j] > mv) || (v[j] == mv && j < t);
        g_mask[b * NTOK + t] = (rank < NMASK) ? 1 : 0;
    }
}

// warp-per-row LayerNorm -> bf16 (no block barriers)
__global__ __launch_bounds__(256) void ln_kernel(const float* __restrict__ x,
                                                 const float* __restrict__ s,
                                                 const float* __restrict__ bp,
                                                 __nv_bfloat16* __restrict__ out) {
    int row = blockIdx.x * 8 + (threadIdx.x >> 5);
    int lane = threadIdx.x & 31;
    const float4* xr = (const float4*)(x + (size_t)row * DIM);
    float4 v[6];
    float s1 = 0.0f, s2 = 0.0f;
    #pragma unroll
    for (int i = 0; i < 6; i++) {
        v[i] = xr[lane + 32 * i];
        s1 += v[i].x + v[i].y + v[i].z + v[i].w;
        s2 += v[i].x * v[i].x + v[i].y * v[i].y + v[i].z * v[i].z + v[i].w * v[i].w;
    }
    #pragma unroll
    for (int o = 16; o; o >>= 1) {
        s1 += __shfl_xor_sync(0xffffffffu, s1, o);
        s2 += __shfl_xor_sync(0xffffffffu, s2, o);
    }
    float mean = s1 * (1.0f / DIM);
    float var  = s2 * (1.0f / DIM) - mean * mean;
    float rstd = rsqrtf(var + 1e-5f);
    const float4* sv = (const float4*)s;
    const float4* bv = (const float4*)bp;
    #pragma unroll
    for (int i = 0; i < 6; i++) {
        float4 sf = sv[lane + 32 * i];
        float4 bf = bv[lane + 32 * i];
        float o0 = (v[i].x - mean) * rstd * sf.x + bf.x;
        float o1 = (v[i].y - mean) * rstd * sf.y + bf.y;
        float o2 = (v[i].z - mean) * rstd * sf.z + bf.z;
        float o3 = (v[i].w - mean) * rstd * sf.w + bf.w;
        __nv_bfloat162 ha, hb;
        ha.x = __float2bfloat16(o0); ha.y = __float2bfloat16(o1);
        hb.x = __float2bfloat16(o2); hb.y = __float2bfloat16(o3);
        uint2 u;
        u.x = *(uint32_t*)&ha; u.y = *(uint32_t*)&hb;
        *(uint2*)(out + (size_t)row * DIM + (lane + 32 * i) * 4) = u;
    }
}

// W[K,N] fp32 -> Wt[N,K] bf16 (z = layer)
__global__ void transpose_w(const float* __restrict__ W,
                            __nv_bfloat16* __restrict__ Wt, int K, int N) {
    __shared__ float t[32][33];
    W  += (size_t)blockIdx.z * K * N;
    Wt += (size_t)blockIdx.z * N * K;
    int bn = blockIdx.x * 32, bk = blockIdx.y * 32;
    int tx = threadIdx.x, ty = threadIdx.y;
    #pragma unroll
    for (int j = 0; j < 32; j += 8)
        t[ty + j][tx] = W[(size_t)(bk + ty + j) * N + bn + tx];
    __syncthreads();
    #pragma unroll
    for (int j = 0; j < 32; j += 8)
        Wt[(size_t)(bn + ty + j) * K + bk + tx] = __float2bfloat16(t[tx][ty + j]);
}

__device__ __forceinline__ float gelu_f(float x) {
    float x3 = x * x * x;
    return 0.5f * x * (1.0f + tanhf(0.7978845608028654f * (x + 0.044715f * x3)));
}

// ============================================================================
// bf16 tensor-core GEMM (unchanged from R14)
// EPI: 0=bias, 1=bias+resid, 2=gelu(bias), 3=bias+posemb/mask
// ============================================================================
#define GSTAGE 32768
#define GSMEM  (3 * GSTAGE)

template<int EPI, bool OF32, bool OB16>
__global__ __launch_bounds__(256) void gemm_mma(
    const __nv_bfloat16* __restrict__ A,
    const __nv_bfloat16* __restrict__ Bt,
    const float* __restrict__ bias,
    const float* __restrict__ resid,
    float* __restrict__ Cf,
    __nv_bfloat16* __restrict__ Cb,
    int N, int K,
    const float* __restrict__ pe,
    const float* __restrict__ mtok)
{
    extern __shared__ __align__(16) char smem[];
    const uint32_t sbase = smem_u32(smem);
    const int tid = threadIdx.x;
    const int wid = tid >> 5, lane = tid & 31;
    const int warpM = wid >> 2;
    const int warpN = wid & 3;
    const int rowBase = blockIdx.y * 128;
    const int colBase = blockIdx.x * 128;
    const int KCH = K >> 6;

    const int lrow = tid >> 1;
    const int lseg = (tid & 1) * 4;
    const __nv_bfloat16* aSrc = A  + (size_t)(rowBase + lrow) * K + lseg * 8;
    const __nv_bfloat16* bSrc = Bt + (size_t)(colBase + lrow) * K + lseg * 8;
    uint32_t dOff[4];
    #pragma unroll
    for (int i = 0; i < 4; i++) dOff[i] = swz64(lrow, lseg + i);

    uint32_t offA[4], offB[2];
    #pragma unroll
    for (int mf = 0; mf < 4; mf++)
        offA[mf] = swz64(warpM * 64 + mf * 16 + (lane & 15), (lane >> 4));
    #pragma unroll
    for (int p = 0; p < 2; p++)
        offB[p] = 16384u + swz64(warpN * 32 + p * 16 + (lane & 7) + ((lane >> 4) << 3),
                                 (lane >> 3) & 1);

    float acc[4][4][4];
    #pragma unroll
    for (int i = 0; i < 4; i++)
        #pragma unroll
        for (int j = 0; j < 4; j++)
            #pragma unroll
            for (int e = 0; e < 4; e++) acc[i][j][e] = 0.0f;

    auto stage_load = [&](int kc, int s) {
        uint32_t st = sbase + (uint32_t)s * GSTAGE;
        const __nv_bfloat16* a = aSrc + kc * 64;
        const __nv_bfloat16* b = bSrc + kc * 64;
        #pragma unroll
        for (int i = 0; i < 4; i++) {
            cp_async16(st + dOff[i], a + i * 8);
            cp_async16(st + 16384 + dOff[i], b + i * 8);
        }
        cp_commit();
    };

    stage_load(0, 0);
    if (KCH > 1) stage_load(1, 1);

    int sIdx = 0;
    for (int c = 0; c < KCH; c++) {
        if (c + 1 < KCH) asm volatile("cp.async.wait_group 1;");
        else             asm volatile("cp.async.wait_group 0;");
        __syncthreads();

        if (c + 2 < KCH) {
            int ns = sIdx + 2; if (ns >= 3) ns -= 3;
            stage_load(c + 2, ns);
        }

        uint32_t base = sbase + (uint32_t)sIdx * GSTAGE;
        #pragma unroll
        for (int kk = 0; kk < 4; kk++) {
            uint32_t x = (uint32_t)kk << 5;
            uint32_t afr[4][4];
            #pragma unroll
            for (int mf = 0; mf < 4; mf++) ldm_x4(afr[mf], base + (offA[mf] ^ x));
            uint32_t bfr[4][2];
            #pragma unroll
            for (int p = 0; p < 2; p++) {
                uint32_t r[4];
                ldm_x4(r, base + (offB[p] ^ x));
                bfr[p * 2][0] = r[0]; bfr[p * 2][1] = r[1];
                bfr[p * 2 + 1][0] = r[2]; bfr[p * 2 + 1][1] = r[3];
            }
            #pragma unroll
            for (int mf = 0; mf < 4; mf++)
                #pragma unroll
                for (int nf = 0; nf < 4; nf++)
                    mma16816(acc[mf][nf], afr[mf], bfr[nf]);
        }
        sIdx++; if (sIdx == 3) sIdx = 0;
    }

    const int rq = lane >> 2;
    const int cq = (lane & 3) * 2;
    #pragma unroll
    for (int mf = 0; mf < 4; mf++) {
        #pragma unroll
        for (int nf = 0; nf < 4; nf++) {
            int col = colBase + warpN * 32 + nf * 8 + cq;
            float b0 = bias[col], b1 = bias[col + 1];
            #pragma unroll
            for (int hrow = 0; hrow < 2; hrow++) {
                int row = rowBase + warpM * 64 + mf * 16 + rq + hrow * 8;
                size_t off = (size_t)row * N + col;
                float v0 = acc[mf][nf][hrow * 2 + 0] + b0;
                float v1 = acc[mf][nf][hrow * 2 + 1] + b1;
                if (EPI == 1) {
                    float2 rv = *(const float2*)(resid + off);
                    v0 += rv.x; v1 += rv.y;
                }
                if (EPI == 2) { v0 = gelu_f(v0); v1 = gelu_f(v1); }
                if (EPI == 3) {
                    int n = row % NTOK;
                    float2 pev = *(const float2*)(pe + (size_t)(n + 1) * DIM + col);
                    if (g_mask[row]) {
                        float2 mt = *(const float2*)(mtok + col);
                        v0 = mt.x + pev.x; v1 = mt.y + pev.y;
                    } else {
                        v0 += pev.x; v1 += pev.y;
                    }
                }
                if (OF32) *(float2*)(Cf + off) = make_float2(v0, v1);
                if (OB16) {
                    __nv_bfloat162 h;
                    h.x = __float2bfloat16(v0); h.y = __float2bfloat16(v1);
                    *(__nv_bfloat162*)(Cb + off) = h;
                }
            }
        }
    }
}

// ============================================================================
// Tensor-core attention. Block = (b,h), 8 warps.
// SMEM: Ks [208][64] bf16 swz64 | Qs [64][64] bf16 swz64 | Vt [64 d][256 k]
// bf16 (512B rows) | Ps [64 q][256 k] bf16 (512B rows) | Ss [64][208] fp32.
// 4 q-chunks of 64 rows (padded; rows>=196 discarded). Key cols >=196 masked.
// ============================================================================
#define AT_KS 0
#define AT_QS 26624
#define AT_VT 34816
#define AT_PS 67584
#define AT_SS 100352
#define ASMEM 153600

__global__ __launch_bounds__(256) void attn_kernel(const float* __restrict__ qkv,
                                                   __nv_bfloat16* __restrict__ out) {
    extern __shared__ __align__(16) char asmem[];
    const uint32_t sb = smem_u32(asmem);
    int bh = blockIdx.x;
    int b = bh / HEADS, h = bh % HEADS;
    const float* Qb = qkv + (size_t)b * NTOK * QKVDIM + h * DH;
    const float* Kb = Qb + DIM;
    const float* Vb = Qb + 2 * DIM;
    int tid = threadIdx.x;
    int w = tid >> 5, lane = tid & 31;
    const int mw = w & 3;     // m16 tile within 64-row chunk
    const int nh = w >> 2;    // n-half for QK / d-half for AV

    // ---- K: 208 rows x 8 segs, bf16, swz64; pad rows zero ----
    for (int idx = tid; idx < 208 * 8; idx += 256) {
        int r = idx >> 3, sg = idx & 7;
        uint4 val = make_uint4(0, 0, 0, 0);
        if (r < NTOK) val = pack8bf(Kb + (size_t)r * QKVDIM + sg * 8);
        *(uint4*)(asmem + AT_KS + swz64(r, sg)) = val;
    }
    // ---- Vt[d][k]: transpose during load; pad k zero ----
    for (int idx = tid; idx < 208 * 64; idx += 256) {
        int k = idx >> 6, d = idx & 63;
        float v = (k < NTOK) ? Vb[(size_t)k * QKVDIM + d] : 0.0f;
        *(__nv_bfloat16*)(asmem + AT_VT + d * 512 + segswz(d, k >> 3) * 16 + (k & 7) * 2)
            = __float2bfloat16(v);
    }
    __syncthreads();

    for (int ch = 0; ch < 4; ch++) {
        // ---- Q chunk: 64 rows x 8 segs ----
        for (int idx = tid; idx < 64 * 8; idx += 256) {
            int r = idx >> 3, sg = idx & 7;
            int qr = ch * 64 + r;
            uint4 val = make_uint4(0, 0, 0, 0);
            if (qr < NTOK) val = pack8bf(Qb + (size_t)qr * QKVDIM + sg * 8);
            *(uint4*)(asmem + AT_QS + swz64(r, sg)) = val;
        }
        __syncthreads();

        // ---- QK: warp = (mw, nh); S tile m16 x 104 (13 n8 tiles) ----
        {
            float acc[13][4];
            #pragma unroll
            for (int nf = 0; nf < 13; nf++)
                #pragma unroll
                for (int e = 0; e < 4; e++) acc[nf][e] = 0.0f;

            #pragma unroll
            for (int kk = 0; kk < 4; kk++) {
                uint32_t afr[4];
                ldm_x4(afr, sb + AT_QS + swz64(mw * 16 + (lane & 15), kk * 2 + (lane >> 4)));
                uint32_t bfr[13][2];
                #pragma unroll
                for (int p = 0; p < 6; p++) {
                    uint32_t r4[4];
                    int row = nh * 104 + p * 16 + (lane & 7) + ((lane >> 4) << 3);
                    ldm_x4(r4, sb + AT_KS + swz64(row, kk * 2 + ((lane >> 3) & 1)));
                    bfr[p * 2][0] = r4[0]; bfr[p * 2][1] = r4[1];
                    bfr[p * 2 + 1][0] = r4[2]; bfr[p * 2 + 1][1] = r4[3];
                }
                {
                    int row = nh * 104 + 96 + (lane & 7);
                    ldm_x2(bfr[12], sb + AT_KS + swz64(row, kk * 2 + ((lane >> 3) & 1)));
                }
                #pragma unroll
                for (int nf = 0; nf < 13; nf++)
                    mma16816(acc[nf], afr, bfr[nf]);
            }
            // write S (fp32)
            #pragma unroll
            for (int nf = 0; nf < 13; nf++) {
                int col = nh * 104 + nf * 8 + 2 * (lane & 3);
                #pragma unroll
                for (int hrow = 0; hrow < 2; hrow++) {
                    int r = mw * 16 + (lane >> 2) + hrow * 8;
                    *(float2*)(asmem + AT_SS + r * 832 + col * 4) =
                        make_float2(acc[nf][hrow * 2], acc[nf][hrow * 2 + 1]);
                }
            }
        }
        __syncthreads();

        // ---- softmax: warp handles rows w*8 .. w*8+7 ----
        for (int rr = 0; rr < 8; rr++) {
            int r = w * 8 + rr;
            float vals[7];
            float mx = -1e30f;
            #pragma unroll
            for (int i = 0; i < 7; i++) {
                int c = lane + 32 * i;
                float s = -1e30f;
                if (c < NTOK)
                    s = *(const float*)(asmem + AT_SS + r * 832 + c * 4) * 0.125f;
                vals[i] = s;
                mx = fmaxf(mx, s);
            }
            #pragma unroll
            for (int o = 16; o; o >>= 1)
                mx = fmaxf(mx, __shfl_xor_sync(0xffffffffu, mx, o));
            float sum = 0.0f;
            #pragma unroll
            for (int i = 0; i < 7; i++) {
                int c = lane + 32 * i;
                float e = (c < NTOK) ? __expf(vals[i] - mx) : 0.0f;
                vals[i] = e;
                sum += e;
            }
            #pragma unroll
            for (int o = 16; o; o >>= 1)
                sum += __shfl_xor_sync(0xffffffffu, sum, o);
            float inv = 1.0f / sum;
            #pragma unroll
            for (int i = 0; i < 7; i++) {
                int c = lane + 32 * i;
                if (c < 208) {
                    float pv = (c < NTOK) ? vals[i] * inv : 0.0f;
                    *(__nv_bfloat16*)(asmem + AT_PS + r * 512 +
                                      segswz(r, c >> 3) * 16 + (c & 7) * 2)
                        = __float2bfloat16(pv);
                }
            }
        }
        __syncthreads();

        // ---- AV: warp = (mw, dh=nh); O tile m16 x 32 (4 n8 tiles) ----
        {
            float acc2[4][4];
            #pragma unroll
            for (int nf = 0; nf < 4; nf++)
                #pragma unroll
                for (int e = 0; e < 4; e++) acc2[nf][e] = 0.0f;

            for (int ks = 0; ks < 13; ks++) {
                uint32_t afr[4];
                {
                    int row = mw * 16 + (lane & 15);
                    int seg = ks * 2 + (lane >> 4);
                    ldm_x4(afr, sb + AT_PS + row * 512 + segswz(row, seg) * 16);
                }
                uint32_t bfr[4][2];
                #pragma unroll
                for (int p = 0; p < 2; p++) {
                    int row = nh * 32 + p * 16 + (lane & 7) + ((lane >> 4) << 3);
                    int seg = ks * 2 + ((lane >> 3) & 1);
                    uint32_t r4[4];
                    ldm_x4(r4, sb + AT_VT + row * 512 + segswz(row, seg) * 16);
                    bfr[p * 2][0] = r4[0]; bfr[p * 2][1] = r4[1];
                    bfr[p * 2 + 1][0] = r4[2]; bfr[p * 2 + 1][1] = r4[3];
                }
                #pragma unroll
                for (int nf = 0; nf < 4; nf++)
                    mma16816(acc2[nf], afr, bfr[nf]);
            }
            // store O
            #pragma unroll
            for (int nf = 0; nf < 4; nf++) {
                int col = h * DH + nh * 32 + nf * 8 + 2 * (lane & 3);
                #pragma unroll
                for (int hrow = 0; hrow < 2; hrow++) {
                    int qr = ch * 64 + mw * 16 + (lane >> 2) + hrow * 8;
                    if (qr < NTOK) {
                        __nv_bfloat162 hv;
                        hv.x = __float2bfloat16(acc2[nf][hrow * 2]);
                        hv.y = __float2bfloat16(acc2[nf][hrow * 2 + 1]);
                        *(__nv_bfloat162*)(out + ((size_t)b * NTOK + qr) * DIM + col) = hv;
                    }
                }
            }
        }
        __syncthreads();
    }
}

// ============================================================================
// Loss
// ============================================================================
__global__ void loss_partial_kernel() {
    double acc = 0.0;
    for (size_t i = (size_t)blockIdx.x * blockDim.x + threadIdx.x;
         i < TOTELEM; i += (size_t)gridDim.x * blockDim.x) {
        int bn = (int)(i / DIM);
        if (g_mask[bn]) acc += fabs((double)g_pred[i] - (double)g_patches[i]);
    }
    __shared__ double red[256];
    red[threadIdx.x] = acc;
    __syncthreads();
    for (int o = 128; o; o >>= 1) {
        if (threadIdx.x < o) red[threadIdx.x] += red[threadIdx.x + o];
        __syncthreads();
    }
    if (threadIdx.x == 0) g_part[blockIdx.x] = red[0];
}

__global__ void loss_final_kernel(float* out) {
    __shared__ double red[256];
    int t = threadIdx.x;
    double a = 0.0;
    for (int i = t; i < 1024; i += 256) a += g_part[i];
    red[t] = a;
    __syncthreads();
    for (int o = 128; o; o >>= 1) { if (t < o) red[t] += red[t + o]; __syncthreads(); }
    if (t == 0) out[0] = (float)(red[0] / (4816896.0 * 98.0));
}

// ============================================================================
// Launch (embed GEMM at launch index 3 = the ncu-captured slot)
// ============================================================================
extern "C" void kernel_launch(void* const* d_in, const int* in_sizes, int n_in,
                              void* d_out, int out_size) {
    const float* img        = (const float*)d_in[0];
    const float* mask_noise = (const float*)d_in[1];
    const float* patch_w    = (const float*)d_in[2];
    const float* patch_b    = (const float*)d_in[3];
    const float* pos_emb    = (const float*)d_in[4];
    const float* mask_token = (const float*)d_in[5];
    const float* ln1_s      = (const float*)d_in[6];
    const float* ln1_b      = (const float*)d_in[7];
    const float* wqkv       = (const float*)d_in[8];
    const float* bqkv       = (const float*)d_in[9];
    const float* wo         = (const float*)d_in[10];
    const float* bo         = (const float*)d_in[11];
    const float* ln2_s      = (const float*)d_in[12];
    const float* ln2_b      = (const float*)d_in[13];
    const float* w1         = (const float*)d_in[14];
    const float* b1         = (const float*)d_in[15];
    const float* w2         = (const float*)d_in[16];
    const float* b2         = (const float*)d_in[17];
    const float* pix_w      = (const float*)d_in[18];
    const float* pix_b      = (const float*)d_in[19];
    float* out = (float*)d_out;

    float *x, *qkv, *pred;
    __nv_bfloat16 *pb, *hb, *ab, *xb, *hidb;
    __nv_bfloat16 *wqkvT, *woT, *w1T, *w2T, *pwT, *pixT;
    cudaGetSymbolAddress((void**)&x,     g_x);
    cudaGetSymbolAddress((void**)&qkv,   g_qkv);
    cudaGetSymbolAddress((void**)&pred,  g_pred);
    cudaGetSymbolAddress((void**)&pb,    g_pb);
    cudaGetSymbolAddress((void**)&hb,    g_hb);
    cudaGetSymbolAddress((void**)&ab,    g_ab);
    cudaGetSymbolAddress((void**)&xb,    g_xb);
    cudaGetSymbolAddress((void**)&hidb,  g_hidb);
    cudaGetSymbolAddress((void**)&wqkvT, g_wqkvT);
    cudaGetSymbolAddress((void**)&woT,   g_woT);
    cudaGetSymbolAddress((void**)&w1T,   g_w1T);
    cudaGetSymbolAddress((void**)&w2T,   g_w2T);
    cudaGetSymbolAddress((void**)&pwT,   g_pwT);
    cudaGetSymbolAddress((void**)&pixT,  g_pixT);

    cudaFuncSetAttribute(gemm_mma<0, true,  false>, cudaFuncAttributeMaxDynamicSharedMemorySize, GSMEM);
    cudaFuncSetAttribute(gemm_mma<1, true,  false>, cudaFuncAttributeMaxDynamicSharedMemorySize, GSMEM);
    cudaFuncSetAttribute(gemm_mma<1, true,  true >, cudaFuncAttributeMaxDynamicSharedMemorySize, GSMEM);
    cudaFuncSetAttribute(gemm_mma<2, false, true >, cudaFuncAttributeMaxDynamicSharedMemorySize, GSMEM);
    cudaFuncSetAttribute(gemm_mma<3, true,  false>, cudaFuncAttributeMaxDynamicSharedMemorySize, GSMEM);
    cudaFuncSetAttribute(attn_kernel, cudaFuncAttributeMaxDynamicSharedMemorySize, ASMEM);

    int eltBlocks = (int)((TOTELEM + 255) / 256);
    dim3 tb(32, 8);

    // launches 0..2
    patchify_kernel<<<eltBlocks, 256>>>(img);                               // 0
    transpose_w<<<dim3(DIM / 32, DIM / 32), tb>>>(patch_w, pwT, DIM, DIM);  // 1
    topk_kernel<<<BATCH, 256>>>(mask_noise);                                // 2
    // launch 3 (profiled): embed GEMM with fused finalize
    gemm_mma<3, true, false><<<dim3(DIM / 128, TOKENS / 128), 256, GSMEM>>>(
        pb, pwT, patch_b, nullptr, x, nullptr, DIM, DIM,
        pos_emb, mask_token);                                               // 3

    // batched weight transposes (z = layer)
    transpose_w<<<dim3(DIM / 32, DIM / 32), tb>>>(pix_w, pixT, DIM, DIM);
    transpose_w<<<dim3(QKVDIM / 32, DIM / 32, DEPTH), tb>>>(wqkv, wqkvT, DIM, QKVDIM);
    transpose_w<<<dim3(DIM / 32, DIM / 32, DEPTH), tb>>>(wo, woT, DIM, DIM);
    transpose_w<<<dim3(MLPDIM / 32, DIM / 32, DEPTH), tb>>>(w1, w1T, DIM, MLPDIM);
    transpose_w<<<dim3(DIM / 32, MLPDIM / 32, DEPTH), tb>>>(w2, w2T, MLPDIM, DIM);

    for (int l = 0; l < DEPTH; l++) {
        ln_kernel<<<TOKENS / 8, 256>>>(x, ln1_s + l * DIM, ln1_b + l * DIM, hb);
        gemm_mma<0, true, false><<<dim3(QKVDIM / 128, TOKENS / 128), 256, GSMEM>>>(
            hb, wqkvT + (size_t)l * QKVDIM * DIM, bqkv + l * QKVDIM, nullptr,
            qkv, nullptr, QKVDIM, DIM, nullptr, nullptr);
        attn_kernel<<<BATCH * HEADS, 256, ASMEM>>>(qkv, ab);
        gemm_mma<1, true, false><<<dim3(DIM / 128, TOKENS / 128), 256, GSMEM>>>(
            ab, woT + (size_t)l * DIM * DIM, bo + l * DIM, x,
            x, nullptr, DIM, DIM, nullptr, nullptr);
        ln_kernel<<<TOKENS / 8, 256>>>(x, ln2_s + l * DIM, ln2_b + l * DIM, hb);
        gemm_mma<2, false, true><<<dim3(MLPDIM / 128, TOKENS / 128), 256, GSMEM>>>(
            hb, w1T + (size_t)l * MLPDIM * DIM, b1 + l * MLPDIM, nullptr,
            nullptr, hidb, MLPDIM, DIM, nullptr, nullptr);
        if (l < DEPTH - 1) {
            gemm_mma<1, true, false><<<dim3(DIM / 128, TOKENS / 128), 256, GSMEM>>>(
                hidb, w2T + (size_t)l * DIM * MLPDIM, b2 + l * DIM, x,
                x, nullptr, DIM, MLPDIM, nullptr, nullptr);
        } else {
            gemm_mma<1, true, true><<<dim3(DIM / 128, TOKENS / 128), 256, GSMEM>>>(
                hidb, w2T + (size_t)l * DIM * MLPDIM, b2 + l * DIM, x,
                x, xb, DIM, MLPDIM, nullptr, nullptr);
        }
    }

    // pixel head
    gemm_mma<0, true, false><<<dim3(DIM / 128, TOKENS / 128), 256, GSMEM>>>(
        xb, pixT, pix_b, nullptr, pred, nullptr, DIM, DIM, nullptr, nullptr);

    loss_partial_kernel<<<1024, 256>>>();
    loss_final_kernel<<<1, 256>>>(out);
}